// round 1
// baseline (speedup 1.0000x reference)
#include <cuda_runtime.h>
#include <math.h>

// Problem constants (match reference)
#define NCc 65536
#define NPc 32768
#define Dc  128
#define Hc  4
#define Cc  128
#define HCc 512
#define Bc  1024
#define Lc  4
#define BWc 7
#define SLOPEc 0.2f

// ---------------- scratch (device globals, no allocation) ----------------
__device__ float g_cell [NCc * Dc];    // 32 MB  current cell features
__device__ float g_acc  [NCc * Dc];    // 32 MB  per-layer accumulator
__device__ float g_piece[NPc * Dc];    // 16 MB  piece features (constant)
__device__ float g_xl   [NCc * HCc];   // 128 MB xl = x_src @ Wl + bl
__device__ float g_xr   [NCc * HCc];   // 128 MB xr = cell @ Wr + br
__device__ float g_score[NCc * Hc];    // per-edge scores / p (E<=65536)
__device__ float g_m    [NCc * Hc];    // segment max
__device__ float g_den  [NCc * Hc];    // segment sum
__device__ float g_sums [Bc * Dc];     // pooling sums
__device__ float g_cnts [Bc];          // pooling counts

// ---------------- helpers ----------------
__device__ __forceinline__ void atomicMaxF(float* addr, float value) {
    if (value >= 0.f) atomicMax((int*)addr, __float_as_int(value));
    else              atomicMin((unsigned int*)addr, __float_as_uint(value));
}

// ---------------- elementwise kernels ----------------
__global__ void k_zero(float* __restrict__ p, int n) {
    int i = blockIdx.x * blockDim.x + threadIdx.x;
    if (i < n) p[i] = 0.f;
}

__global__ void k_init_md(float* __restrict__ m, float* __restrict__ den, int n) {
    int i = blockIdx.x * blockDim.x + threadIdx.x;
    if (i < n) { m[i] = __int_as_float(0xff800000); den[i] = 0.f; } // -inf, 0
}

__global__ void k_embed(const int* __restrict__ idx, const float* __restrict__ emb,
                        float* __restrict__ out, int n) {
    int i = blockIdx.x * blockDim.x + threadIdx.x;
    if (i < n) out[i] = emb[idx[i >> 7] * Dc + (i & 127)];
}

// cell = relu(acc + sum_r conv_bias[l,r,:])   (cb points to conv_bias[l,0,0], 3*128 floats)
__global__ void k_relu_bias(float* __restrict__ cell, const float* __restrict__ acc,
                            const float* __restrict__ cb, int n) {
    int i = blockIdx.x * blockDim.x + threadIdx.x;
    if (i < n) {
        int c = i & 127;
        float b = cb[c] + cb[128 + c] + cb[256 + c];
        cell[i] = fmaxf(acc[i] + b, 0.f);
    }
}

// ---------------- GEMM: C[M,512] = A[M,128] @ W[128,512] + bias[512] ----------------
// BM=64, BN=64, BK=16, 256 threads, 4x4 per thread
__global__ void k_gemm_bias(const float* __restrict__ A, const float* __restrict__ W,
                            const float* __restrict__ bias, float* __restrict__ C, int M) {
    const int N = 512, K = 128;
    __shared__ float As[16][64];
    __shared__ float Bs[16][64];
    int bx = blockIdx.x;            // N tiles: 8
    int by = blockIdx.y;            // M tiles
    int tid = threadIdx.x;          // 256
    int tx = tid & 15, ty = tid >> 4;
    int row0 = by * 64;

    float acc[4][4];
#pragma unroll
    for (int i = 0; i < 4; i++)
#pragma unroll
        for (int j = 0; j < 4; j++) acc[i][j] = 0.f;

    for (int k0 = 0; k0 < K; k0 += 16) {
        // load A tile 64x16 (256 float4)
        {
            int m  = tid >> 2;
            int k4 = (tid & 3) * 4;
            float4 v = *(const float4*)&A[(size_t)(row0 + m) * K + k0 + k4];
            As[k4 + 0][m] = v.x; As[k4 + 1][m] = v.y;
            As[k4 + 2][m] = v.z; As[k4 + 3][m] = v.w;
        }
        // load W tile 16x64 (256 float4)
        {
            int k  = tid >> 4;
            int n4 = (tid & 15) * 4;
            float4 v = *(const float4*)&W[(size_t)(k0 + k) * N + bx * 64 + n4];
            *(float4*)&Bs[k][n4] = v;
        }
        __syncthreads();
#pragma unroll
        for (int k = 0; k < 16; k++) {
            float a[4];
            float4 b4 = *(const float4*)&Bs[k][tx * 4];
            float b[4] = {b4.x, b4.y, b4.z, b4.w};
#pragma unroll
            for (int i = 0; i < 4; i++) a[i] = As[k][ty * 4 + i];
#pragma unroll
            for (int i = 0; i < 4; i++)
#pragma unroll
                for (int j = 0; j < 4; j++) acc[i][j] += a[i] * b[j];
        }
        __syncthreads();
    }
#pragma unroll
    for (int i = 0; i < 4; i++) {
        int r = row0 + ty * 4 + i;
#pragma unroll
        for (int j = 0; j < 4; j++) {
            int cidx = bx * 64 + tx * 4 + j;
            C[(size_t)r * N + cidx] = acc[i][j] + bias[cidx];
        }
    }
}

// ---------------- edge kernels (warp per edge) ----------------
// score[e,h] = sum_c att[h,c]*leaky_relu(xl[src,h,c]+xr[dst,h,c]); atomicMax into m[dst,h]
__global__ void k_score(const float* __restrict__ xl, const float* __restrict__ xr,
                        const int* __restrict__ src, const int* __restrict__ dst,
                        const float* __restrict__ att, float* __restrict__ score,
                        float* __restrict__ m, int E) {
    int e = blockIdx.x * (blockDim.x >> 5) + (threadIdx.x >> 5);
    int lane = threadIdx.x & 31;
    if (e >= E) return;
    int s = src[e], d = dst[e];
    const float* xls = xl + (size_t)s * HCc;
    const float* xrd = xr + (size_t)d * HCc;
    float part[4] = {0.f, 0.f, 0.f, 0.f};
#pragma unroll
    for (int k = 0; k < 16; k++) {
        int idx = lane + 32 * k;
        float v = xls[idx] + xrd[idx];
        v = v > 0.f ? v : SLOPEc * v;
        part[k >> 2] += v * att[idx];
    }
#pragma unroll
    for (int h = 0; h < 4; h++) {
        float v = part[h];
#pragma unroll
        for (int off = 16; off; off >>= 1) v += __shfl_down_sync(0xffffffffu, v, off);
        if (lane == 0) {
            score[e * 4 + h] = v;
            atomicMaxF(&m[d * 4 + h], v);
        }
    }
}

// p = exp(score - m[dst]); atomicAdd denom
__global__ void k_softmax_p(const int* __restrict__ dst, const float* __restrict__ m,
                            float* __restrict__ score, float* __restrict__ den, int E4) {
    int i = blockIdx.x * blockDim.x + threadIdx.x;
    if (i >= E4) return;
    int e = i >> 2, h = i & 3;
    int d = dst[e];
    float p = expf(score[i] - m[d * 4 + h]);
    score[i] = p;
    atomicAdd(&den[d * 4 + h], p);
}

// acc[dst,c] += (1/H) * sum_h alpha[e,h] * xl[src,h,c]
__global__ void k_aggr(const float* __restrict__ xl, const int* __restrict__ src,
                       const int* __restrict__ dst, const float* __restrict__ p,
                       const float* __restrict__ den, float* __restrict__ acc, int E) {
    int e = blockIdx.x * (blockDim.x >> 5) + (threadIdx.x >> 5);
    int lane = threadIdx.x & 31;
    if (e >= E) return;
    int s = src[e], d = dst[e];
    float alpha[4];
#pragma unroll
    for (int h = 0; h < 4; h++)
        alpha[h] = p[e * 4 + h] / (den[d * 4 + h] + 1e-16f);
    const float* xls = xl + (size_t)s * HCc;
    float* accd = acc + (size_t)d * Dc;
#pragma unroll
    for (int j = 0; j < 4; j++) {
        int c = lane + 32 * j;
        float v = 0.f;
#pragma unroll
        for (int h = 0; h < 4; h++) v += alpha[h] * xls[h * 128 + c];
        atomicAdd(&accd[c], 0.25f * v);
    }
}

// ---------------- pooling ----------------
__global__ void k_pool_add(const float* __restrict__ cell, const int* __restrict__ batch,
                           float* __restrict__ sums, int n) {
    int i = blockIdx.x * blockDim.x + threadIdx.x;
    if (i < n) atomicAdd(&sums[batch[i >> 7] * Dc + (i & 127)], cell[i]);
}

__global__ void k_cnt(const int* __restrict__ batch, float* __restrict__ cnts, int n) {
    int i = blockIdx.x * blockDim.x + threadIdx.x;
    if (i < n) atomicAdd(&cnts[batch[i]], 1.f);
}

// ---------------- heads: one block (64 threads) per graph ----------------
__global__ void k_head(const float* __restrict__ sums, const float* __restrict__ cnts,
                       const float* __restrict__ fc1W, const float* __restrict__ fc1b,
                       const float* __restrict__ polW, const float* __restrict__ polb,
                       const float* __restrict__ valW, const float* __restrict__ valb,
                       float* __restrict__ out_policy, float* __restrict__ out_value) {
    int b = blockIdx.x;
    int t = threadIdx.x;  // 64
    __shared__ float pooled[128];
    __shared__ float hsh[64];
    float cnt = fmaxf(cnts[b], 1.f);
    pooled[t]      = sums[b * Dc + t] / cnt;
    pooled[t + 64] = sums[b * Dc + 64 + t] / cnt;
    __syncthreads();
    float a = fc1b[t];
#pragma unroll 4
    for (int d = 0; d < 128; d++) a += pooled[d] * fc1W[d * 64 + t];
    hsh[t] = fmaxf(a, 0.f);
    __syncthreads();
    if (t < BWc) {
        float a2 = polb[t];
#pragma unroll 4
        for (int k = 0; k < 64; k++) a2 += hsh[k] * polW[k * BWc + t];
        out_policy[b * BWc + t] = a2;
    }
    if (t == 8) {
        float a2 = valb[0];
#pragma unroll 4
        for (int k = 0; k < 64; k++) a2 += hsh[k] * valW[k];
        out_value[b] = tanhf(a2);
    }
}

// ---------------- launch ----------------
extern "C" void kernel_launch(void* const* d_in, const int* in_sizes, int n_in,
                              void* d_out, int out_size) {
    const int* cell_x     = (const int*)d_in[0];
    const int* piece_x    = (const int*)d_in[1];
    const int* srcs[3]    = {(const int*)d_in[2], (const int*)d_in[4], (const int*)d_in[6]};
    const int* dsts[3]    = {(const int*)d_in[3], (const int*)d_in[5], (const int*)d_in[7]};
    const int  Es[3]      = {in_sizes[2], in_sizes[4], in_sizes[6]};
    const int* cell_batch = (const int*)d_in[8];
    const float* cell_emb  = (const float*)d_in[9];
    const float* piece_emb = (const float*)d_in[10];
    const float* Wl  = (const float*)d_in[11];
    const float* bl  = (const float*)d_in[12];
    const float* Wr  = (const float*)d_in[13];
    const float* br  = (const float*)d_in[14];
    const float* att = (const float*)d_in[15];
    const float* cb  = (const float*)d_in[16];
    const float* fc1W = (const float*)d_in[17];
    const float* fc1b = (const float*)d_in[18];
    const float* polW = (const float*)d_in[19];
    const float* polb = (const float*)d_in[20];
    const float* valW = (const float*)d_in[21];
    const float* valb = (const float*)d_in[22];

    const int NC = in_sizes[0];
    const int NP = in_sizes[1];

    float *p_cell, *p_acc, *p_piece, *p_xl, *p_xr, *p_score, *p_m, *p_den, *p_sums, *p_cnts;
    cudaGetSymbolAddress((void**)&p_cell,  g_cell);
    cudaGetSymbolAddress((void**)&p_acc,   g_acc);
    cudaGetSymbolAddress((void**)&p_piece, g_piece);
    cudaGetSymbolAddress((void**)&p_xl,    g_xl);
    cudaGetSymbolAddress((void**)&p_xr,    g_xr);
    cudaGetSymbolAddress((void**)&p_score, g_score);
    cudaGetSymbolAddress((void**)&p_m,     g_m);
    cudaGetSymbolAddress((void**)&p_den,   g_den);
    cudaGetSymbolAddress((void**)&p_sums,  g_sums);
    cudaGetSymbolAddress((void**)&p_cnts,  g_cnts);

    const int T = 256;

    // initial embeddings
    k_embed<<<(NC * Dc + T - 1) / T, T>>>(cell_x, cell_emb, p_cell, NC * Dc);
    k_embed<<<(NP * Dc + T - 1) / T, T>>>(piece_x, piece_emb, p_piece, NP * Dc);

    for (int l = 0; l < Lc; l++) {
        k_zero<<<(NC * Dc + T - 1) / T, T>>>(p_acc, NC * Dc);
        for (int r = 0; r < 3; r++) {
            const float* Asrc = (r == 0) ? p_piece : p_cell;
            int M = (r == 0) ? NP : NC;
            size_t woff = (size_t)(l * 3 + r) * Dc * HCc;
            size_t boff = (size_t)(l * 3 + r) * HCc;

            k_gemm_bias<<<dim3(8, (M + 63) / 64),  T>>>(Asrc,  Wl + woff, bl + boff, p_xl, M);
            k_gemm_bias<<<dim3(8, (NC + 63) / 64), T>>>(p_cell, Wr + woff, br + boff, p_xr, NC);

            k_init_md<<<(NC * Hc + T - 1) / T, T>>>(p_m, p_den, NC * Hc);

            int E = Es[r];
            int warpsPerBlk = T / 32;
            k_score<<<(E + warpsPerBlk - 1) / warpsPerBlk, T>>>(
                p_xl, p_xr, srcs[r], dsts[r], att + (size_t)(l * 3 + r) * HCc, p_score, p_m, E);
            k_softmax_p<<<(E * 4 + T - 1) / T, T>>>(dsts[r], p_m, p_score, p_den, E * 4);
            k_aggr<<<(E + warpsPerBlk - 1) / warpsPerBlk, T>>>(
                p_xl, srcs[r], dsts[r], p_score, p_den, p_acc, E);
        }
        k_relu_bias<<<(NC * Dc + T - 1) / T, T>>>(p_cell, p_acc, cb + (size_t)l * 3 * Cc, NC * Dc);
    }

    // global mean pool
    k_zero<<<(Bc * Dc + T - 1) / T, T>>>(p_sums, Bc * Dc);
    k_zero<<<(Bc + T - 1) / T, T>>>(p_cnts, Bc);
    k_pool_add<<<(NC * Dc + T - 1) / T, T>>>(p_cell, cell_batch, p_sums, NC * Dc);
    k_cnt<<<(NC + T - 1) / T, T>>>(cell_batch, p_cnts, NC);

    // heads: policy [B,7] then value [B,1] concatenated in d_out
    float* out = (float*)d_out;
    k_head<<<Bc, 64>>>(p_sums, p_cnts, fc1W, fc1b, polW, polb, valW, valb,
                       out, out + (size_t)Bc * BWc);
}

// round 3
// speedup vs baseline: 2.3305x; 2.3305x over previous
#include <cuda_runtime.h>
#include <cstdint>
#include <math.h>

// Problem constants (match reference)
#define NCc 65536
#define NPc 32768
#define Dc  128
#define Hc  4
#define Cc  128
#define HCc 512
#define Bc  1024
#define Lc  4
#define BWc 7
#define SLOPEc 0.2f

// ---------------- scratch (device globals, no allocation) ----------------
__device__ float g_cell [NCc * Dc];    // 32 MB  current cell features
__device__ float g_acc  [NCc * Dc];    // 32 MB  per-layer accumulator
__device__ float g_piece[NPc * Dc];    // 16 MB  piece features (constant)
__device__ float g_xl   [NCc * HCc];   // 128 MB xl = x_src @ Wl + bl
__device__ float g_xr   [NCc * HCc];   // 128 MB xr = cell @ Wr + br
__device__ float g_score[NCc * Hc];    // per-edge scores / p
__device__ float g_m    [NCc * Hc];    // segment max
__device__ float g_den  [NCc * Hc];    // segment sum
__device__ float g_sums [Bc * Dc];     // pooling sums
__device__ float g_cnts [Bc];          // pooling counts

// ---------------- helpers ----------------
__device__ __forceinline__ void atomicMaxF(float* addr, float value) {
    if (value >= 0.f) atomicMax((int*)addr, __float_as_int(value));
    else              atomicMin((unsigned int*)addr, __float_as_uint(value));
}

__device__ __forceinline__ uint32_t f2tf32(float x) {
    uint32_t r;
    asm("cvt.rna.tf32.f32 %0, %1;" : "=r"(r) : "f"(x));
    return r;
}

__device__ __forceinline__ void mma_tf32(float* c, const uint32_t* a, const uint32_t* b) {
    asm volatile(
        "mma.sync.aligned.m16n8k8.row.col.f32.tf32.tf32.f32 "
        "{%0,%1,%2,%3}, {%4,%5,%6,%7}, {%8,%9}, {%0,%1,%2,%3};"
        : "+f"(c[0]), "+f"(c[1]), "+f"(c[2]), "+f"(c[3])
        : "r"(a[0]), "r"(a[1]), "r"(a[2]), "r"(a[3]), "r"(b[0]), "r"(b[1]));
}

// ---------------- tf32 mma GEMM: C[M,512] = A[M,128] @ W[128,512] + bias ----------------
// Tile BM=128, BN=128, full K=128 in smem. 256 threads = 8 warps (4x2), warp tile 32x64.
#define LDAS 132
__global__ __launch_bounds__(256, 1)
void k_gemm_tf32(const float* __restrict__ A, const float* __restrict__ W,
                 const float* __restrict__ bias, float* __restrict__ C, int M) {
    extern __shared__ uint32_t smem[];
    uint32_t* As = smem;                 // [128][132] tf32
    uint32_t* Bs = smem + 128 * LDAS;    // [128][132] tf32  (Bs[k][n])
    int tid = threadIdx.x;
    int m0 = blockIdx.y * 128, n0 = blockIdx.x * 128;

    // load A tile 128x128 (16 float4 per thread)
#pragma unroll
    for (int it = 0; it < 16; it++) {
        int idx = tid + it * 256;            // 0..4095
        int r = idx >> 5, c4 = (idx & 31) << 2;
        int gr = m0 + r;
        float4 v = (gr < M) ? *(const float4*)&A[(size_t)gr * Dc + c4]
                            : make_float4(0.f, 0.f, 0.f, 0.f);
        uint32_t* p = &As[r * LDAS + c4];
        p[0] = f2tf32(v.x); p[1] = f2tf32(v.y); p[2] = f2tf32(v.z); p[3] = f2tf32(v.w);
    }
    // load W tile 128x128
#pragma unroll
    for (int it = 0; it < 16; it++) {
        int idx = tid + it * 256;
        int k = idx >> 5, c4 = (idx & 31) << 2;
        float4 v = *(const float4*)&W[(size_t)k * HCc + n0 + c4];
        uint32_t* p = &Bs[k * LDAS + c4];
        p[0] = f2tf32(v.x); p[1] = f2tf32(v.y); p[2] = f2tf32(v.z); p[3] = f2tf32(v.w);
    }
    __syncthreads();

    int lane = tid & 31, wid = tid >> 5;
    int wm = (wid & 3) * 32;     // warp row offset in tile
    int wn = (wid >> 2) * 64;    // warp col offset in tile
    int gid = lane >> 2, tig = lane & 3;

    float acc[2][8][4];
#pragma unroll
    for (int mt = 0; mt < 2; mt++)
#pragma unroll
        for (int nt = 0; nt < 8; nt++)
#pragma unroll
            for (int q = 0; q < 4; q++) acc[mt][nt][q] = 0.f;

#pragma unroll
    for (int k = 0; k < 128; k += 8) {
        uint32_t a[2][4], b[8][2];
#pragma unroll
        for (int mt = 0; mt < 2; mt++) {
            int r = wm + mt * 16 + gid;
            a[mt][0] = As[r * LDAS + k + tig];
            a[mt][1] = As[(r + 8) * LDAS + k + tig];
            a[mt][2] = As[r * LDAS + k + tig + 4];
            a[mt][3] = As[(r + 8) * LDAS + k + tig + 4];
        }
#pragma unroll
        for (int nt = 0; nt < 8; nt++) {
            int c = wn + nt * 8 + gid;
            b[nt][0] = Bs[(k + tig) * LDAS + c];
            b[nt][1] = Bs[(k + tig + 4) * LDAS + c];
        }
#pragma unroll
        for (int mt = 0; mt < 2; mt++)
#pragma unroll
            for (int nt = 0; nt < 8; nt++)
                mma_tf32(acc[mt][nt], a[mt], b[nt]);
    }

    // epilogue: c0/c1 -> row gid, cols tig*2,tig*2+1 ; c2/c3 -> row gid+8
#pragma unroll
    for (int mt = 0; mt < 2; mt++) {
        int r0 = m0 + wm + mt * 16 + gid;
#pragma unroll
        for (int nt = 0; nt < 8; nt++) {
            int col = n0 + wn + nt * 8 + tig * 2;
            float2 bv = *(const float2*)&bias[col];
            if (r0 < M) {
                float2 o0 = make_float2(acc[mt][nt][0] + bv.x, acc[mt][nt][1] + bv.y);
                *(float2*)&C[(size_t)r0 * HCc + col] = o0;
            }
            if (r0 + 8 < M) {
                float2 o1 = make_float2(acc[mt][nt][2] + bv.x, acc[mt][nt][3] + bv.y);
                *(float2*)&C[(size_t)(r0 + 8) * HCc + col] = o1;
            }
        }
    }
}

// ---------------- elementwise kernels (float4) ----------------
__global__ void k_zero4(float4* __restrict__ p, int n4) {
    int i = blockIdx.x * blockDim.x + threadIdx.x;
    if (i < n4) p[i] = make_float4(0.f, 0.f, 0.f, 0.f);
}

__global__ void k_init_md(float* __restrict__ m, float* __restrict__ den, int n) {
    int i = blockIdx.x * blockDim.x + threadIdx.x;
    if (i < n) { m[i] = __int_as_float(0xff800000); den[i] = 0.f; }
}

__global__ void k_embed4(const int* __restrict__ idx, const float4* __restrict__ emb,
                         float4* __restrict__ out, int n4) {
    int i = blockIdx.x * blockDim.x + threadIdx.x;
    if (i < n4) out[i] = emb[idx[i >> 5] * 32 + (i & 31)];
}

// cell = relu(acc + sum_r conv_bias[l,r,:])
__global__ void k_relu_bias4(float4* __restrict__ cell, const float4* __restrict__ acc,
                             const float* __restrict__ cb, int n4) {
    int i = blockIdx.x * blockDim.x + threadIdx.x;
    if (i < n4) {
        int c = (i & 31) * 4;
        float4 a = acc[i];
        float4 o;
        o.x = fmaxf(a.x + cb[c + 0] + cb[128 + c + 0] + cb[256 + c + 0], 0.f);
        o.y = fmaxf(a.y + cb[c + 1] + cb[128 + c + 1] + cb[256 + c + 1], 0.f);
        o.z = fmaxf(a.z + cb[c + 2] + cb[128 + c + 2] + cb[256 + c + 2], 0.f);
        o.w = fmaxf(a.w + cb[c + 3] + cb[128 + c + 3] + cb[256 + c + 3], 0.f);
        cell[i] = o;
    }
}

// ---------------- edge kernels (warp per edge) ----------------
__global__ void k_score(const float* __restrict__ xl, const float* __restrict__ xr,
                        const int* __restrict__ src, const int* __restrict__ dst,
                        const float* __restrict__ att, float* __restrict__ score,
                        float* __restrict__ m, int E) {
    int e = blockIdx.x * (blockDim.x >> 5) + (threadIdx.x >> 5);
    int lane = threadIdx.x & 31;
    if (e >= E) return;
    int s = src[e], d = dst[e];
    const float* xls = xl + (size_t)s * HCc;
    const float* xrd = xr + (size_t)d * HCc;
    float part[4] = {0.f, 0.f, 0.f, 0.f};
#pragma unroll
    for (int k = 0; k < 16; k++) {
        int idx = lane + 32 * k;
        float v = xls[idx] + xrd[idx];
        v = v > 0.f ? v : SLOPEc * v;
        part[k >> 2] += v * att[idx];
    }
#pragma unroll
    for (int h = 0; h < 4; h++) {
        float v = part[h];
#pragma unroll
        for (int off = 16; off; off >>= 1) v += __shfl_down_sync(0xffffffffu, v, off);
        if (lane == 0) {
            score[e * 4 + h] = v;
            atomicMaxF(&m[d * 4 + h], v);
        }
    }
}

__global__ void k_softmax_p(const int* __restrict__ dst, const float* __restrict__ m,
                            float* __restrict__ score, float* __restrict__ den, int E4) {
    int i = blockIdx.x * blockDim.x + threadIdx.x;
    if (i >= E4) return;
    int e = i >> 2, h = i & 3;
    int d = dst[e];
    float p = expf(score[i] - m[d * 4 + h]);
    score[i] = p;
    atomicAdd(&den[d * 4 + h], p);
}

__global__ void k_aggr(const float* __restrict__ xl, const int* __restrict__ src,
                       const int* __restrict__ dst, const float* __restrict__ p,
                       const float* __restrict__ den, float* __restrict__ acc, int E) {
    int e = blockIdx.x * (blockDim.x >> 5) + (threadIdx.x >> 5);
    int lane = threadIdx.x & 31;
    if (e >= E) return;
    int s = src[e], d = dst[e];
    float alpha[4];
#pragma unroll
    for (int h = 0; h < 4; h++)
        alpha[h] = p[e * 4 + h] / (den[d * 4 + h] + 1e-16f);
    const float* xls = xl + (size_t)s * HCc;
    float* accd = acc + (size_t)d * Dc;
#pragma unroll
    for (int j = 0; j < 4; j++) {
        int c = lane + 32 * j;
        float v = 0.f;
#pragma unroll
        for (int h = 0; h < 4; h++) v += alpha[h] * xls[h * 128 + c];
        atomicAdd(&accd[c], 0.25f * v);
    }
}

// ---------------- pooling ----------------
__global__ void k_pool_add(const float* __restrict__ cell, const int* __restrict__ batch,
                           float* __restrict__ sums, int n) {
    int i = blockIdx.x * blockDim.x + threadIdx.x;
    if (i < n) atomicAdd(&sums[batch[i >> 7] * Dc + (i & 127)], cell[i]);
}

__global__ void k_cnt(const int* __restrict__ batch, float* __restrict__ cnts, int n) {
    int i = blockIdx.x * blockDim.x + threadIdx.x;
    if (i < n) atomicAdd(&cnts[batch[i]], 1.f);
}

// ---------------- heads ----------------
__global__ void k_head(const float* __restrict__ sums, const float* __restrict__ cnts,
                       const float* __restrict__ fc1W, const float* __restrict__ fc1b,
                       const float* __restrict__ polW, const float* __restrict__ polb,
                       const float* __restrict__ valW, const float* __restrict__ valb,
                       float* __restrict__ out_policy, float* __restrict__ out_value) {
    int b = blockIdx.x;
    int t = threadIdx.x;  // 64
    __shared__ float pooled[128];
    __shared__ float hsh[64];
    float cnt = fmaxf(cnts[b], 1.f);
    pooled[t]      = sums[b * Dc + t] / cnt;
    pooled[t + 64] = sums[b * Dc + 64 + t] / cnt;
    __syncthreads();
    float a = fc1b[t];
#pragma unroll 4
    for (int d = 0; d < 128; d++) a += pooled[d] * fc1W[d * 64 + t];
    hsh[t] = fmaxf(a, 0.f);
    __syncthreads();
    if (t < BWc) {
        float a2 = polb[t];
#pragma unroll 4
        for (int k = 0; k < 64; k++) a2 += hsh[k] * polW[k * BWc + t];
        out_policy[b * BWc + t] = a2;
    }
    if (t == 8) {
        float a2 = valb[0];
#pragma unroll 4
        for (int k = 0; k < 64; k++) a2 += hsh[k] * valW[k];
        out_value[b] = tanhf(a2);
    }
}

// ---------------- launch ----------------
extern "C" void kernel_launch(void* const* d_in, const int* in_sizes, int n_in,
                              void* d_out, int out_size) {
    const int* cell_x     = (const int*)d_in[0];
    const int* piece_x    = (const int*)d_in[1];
    const int* srcs[3]    = {(const int*)d_in[2], (const int*)d_in[4], (const int*)d_in[6]};
    const int* dsts[3]    = {(const int*)d_in[3], (const int*)d_in[5], (const int*)d_in[7]};
    const int  Es[3]      = {in_sizes[2], in_sizes[4], in_sizes[6]};
    const int* cell_batch = (const int*)d_in[8];
    const float* cell_emb  = (const float*)d_in[9];
    const float* piece_emb = (const float*)d_in[10];
    const float* Wl  = (const float*)d_in[11];
    const float* bl  = (const float*)d_in[12];
    const float* Wr  = (const float*)d_in[13];
    const float* br  = (const float*)d_in[14];
    const float* att = (const float*)d_in[15];
    const float* cb  = (const float*)d_in[16];
    const float* fc1W = (const float*)d_in[17];
    const float* fc1b = (const float*)d_in[18];
    const float* polW = (const float*)d_in[19];
    const float* polb = (const float*)d_in[20];
    const float* valW = (const float*)d_in[21];
    const float* valb = (const float*)d_in[22];

    const int NC = in_sizes[0];
    const int NP = in_sizes[1];

    float *p_cell, *p_acc, *p_piece, *p_xl, *p_xr, *p_score, *p_m, *p_den, *p_sums, *p_cnts;
    cudaGetSymbolAddress((void**)&p_cell,  g_cell);
    cudaGetSymbolAddress((void**)&p_acc,   g_acc);
    cudaGetSymbolAddress((void**)&p_piece, g_piece);
    cudaGetSymbolAddress((void**)&p_xl,    g_xl);
    cudaGetSymbolAddress((void**)&p_xr,    g_xr);
    cudaGetSymbolAddress((void**)&p_score, g_score);
    cudaGetSymbolAddress((void**)&p_m,     g_m);
    cudaGetSymbolAddress((void**)&p_den,   g_den);
    cudaGetSymbolAddress((void**)&p_sums,  g_sums);
    cudaGetSymbolAddress((void**)&p_cnts,  g_cnts);

    const int SMEM_GEMM = 2 * 128 * LDAS * 4;  // 135168 B
    cudaFuncSetAttribute(k_gemm_tf32, cudaFuncAttributeMaxDynamicSharedMemorySize, SMEM_GEMM);

    const int T = 256;

    // initial embeddings
    k_embed4<<<(NC * 32 + T - 1) / T, T>>>(cell_x, (const float4*)cell_emb, (float4*)p_cell, NC * 32);
    k_embed4<<<(NP * 32 + T - 1) / T, T>>>(piece_x, (const float4*)piece_emb, (float4*)p_piece, NP * 32);

    for (int l = 0; l < Lc; l++) {
        k_zero4<<<(NC * 32 + T - 1) / T, T>>>((float4*)p_acc, NC * 32);
        for (int r = 0; r < 3; r++) {
            const float* Asrc = (r == 0) ? p_piece : p_cell;
            int M = (r == 0) ? NP : NC;
            int mat = l * 3 + r;
            size_t woff = (size_t)mat * Dc * HCc;
            size_t boff = (size_t)mat * HCc;

            k_gemm_tf32<<<dim3(4, (M + 127) / 128), 256, SMEM_GEMM>>>(
                Asrc, Wl + woff, bl + boff, p_xl, M);
            k_gemm_tf32<<<dim3(4, (NC + 127) / 128), 256, SMEM_GEMM>>>(
                p_cell, Wr + woff, br + boff, p_xr, NC);

            k_init_md<<<(NC * Hc + T - 1) / T, T>>>(p_m, p_den, NC * Hc);

            int E = Es[r];
            int warpsPerBlk = T / 32;
            k_score<<<(E + warpsPerBlk - 1) / warpsPerBlk, T>>>(
                p_xl, p_xr, srcs[r], dsts[r], att + (size_t)mat * HCc, p_score, p_m, E);
            k_softmax_p<<<(E * 4 + T - 1) / T, T>>>(dsts[r], p_m, p_score, p_den, E * 4);
            k_aggr<<<(E + warpsPerBlk - 1) / warpsPerBlk, T>>>(
                p_xl, srcs[r], dsts[r], p_score, p_den, p_acc, E);
        }
        k_relu_bias4<<<(NC * 32 + T - 1) / T, T>>>(
            (float4*)p_cell, (const float4*)p_acc, cb + (size_t)l * 3 * Cc, NC * 32);
    }

    // global mean pool
    k_zero4<<<(Bc * 32 + T - 1) / T, T>>>((float4*)p_sums, Bc * 32);
    k_zero4<<<(Bc / 4 + T - 1) / T, T>>>((float4*)p_cnts, Bc / 4);
    k_pool_add<<<(NC * Dc + T - 1) / T, T>>>(p_cell, cell_batch, p_sums, NC * Dc);
    k_cnt<<<(NC + T - 1) / T, T>>>(cell_batch, p_cnts, NC);

    // heads: policy [B,7] then value [B,1]
    float* out = (float*)d_out;
    k_head<<<Bc, 64>>>(p_sums, p_cnts, fc1W, fc1b, polW, polb, valW, valb,
                       out, out + (size_t)Bc * BWc);
}

// round 4
// speedup vs baseline: 2.6803x; 1.1501x over previous
#include <cuda_runtime.h>
#include <cstdint>
#include <math.h>

// Problem constants
#define NCc 65536
#define NPc 32768
#define Dc  128
#define Hc  4
#define Cc  128
#define HCc 512
#define Bc  1024
#define Lc  4
#define BWc 7
#define SLOPEc 0.2f

// ---------------- scratch (device globals) ----------------
__device__ float g_cell [NCc * Dc];
__device__ float g_acc  [NCc * Dc];
__device__ float g_piece[NPc * Dc];
__device__ float g_xl0  [NPc * HCc];
__device__ float g_xl1  [NCc * HCc];
__device__ float g_xl2  [NCc * HCc];
__device__ float g_xr0  [NCc * HCc];
__device__ float g_xr1  [NCc * HCc];
__device__ float g_xr2  [NCc * HCc];
__device__ float g_sc   [3][NCc * Hc];
__device__ float g_m    [3][NCc * Hc];
__device__ float g_den  [3][NCc * Hc];
__device__ float g_sums [Bc * Dc];
__device__ float g_cnts [Bc];
__device__ float g_wt   [24 * HCc * Dc];   // pre-rounded, transposed weights [mat][n=512][k=128]

// ---------------- helpers ----------------
__device__ __forceinline__ void atomicMaxF(float* addr, float value) {
    if (value >= 0.f) atomicMax((int*)addr, __float_as_int(value));
    else              atomicMin((unsigned int*)addr, __float_as_uint(value));
}
__device__ __forceinline__ float f2tf32f(float x) {
    uint32_t r;
    asm("cvt.rna.tf32.f32 %0, %1;" : "=r"(r) : "f"(x));
    return __uint_as_float(r);
}
__device__ __forceinline__ void mma_tf32(float* c, const uint32_t* a, uint32_t b0, uint32_t b1) {
    asm volatile(
        "mma.sync.aligned.m16n8k8.row.col.f32.tf32.tf32.f32 "
        "{%0,%1,%2,%3}, {%4,%5,%6,%7}, {%8,%9}, {%0,%1,%2,%3};"
        : "+f"(c[0]), "+f"(c[1]), "+f"(c[2]), "+f"(c[3])
        : "r"(a[0]), "r"(a[1]), "r"(a[2]), "r"(a[3]), "r"(b0), "r"(b1));
}

// ---------------- weight prep: round to tf32 + transpose [k][n] -> [n][k] ----------------
__global__ void k_wprep(const float* __restrict__ W, float* __restrict__ WT) {
    __shared__ float t[32][33];
    int mat = blockIdx.z;
    int n0 = blockIdx.x * 32, k0 = blockIdx.y * 32;
    int x = threadIdx.x, y = threadIdx.y;
    const float* w  = W  + (size_t)mat * Dc * HCc;
    float*       wt = WT + (size_t)mat * Dc * HCc;
#pragma unroll
    for (int j = 0; j < 4; j++)
        t[y + 8 * j][x] = w[(size_t)(k0 + y + 8 * j) * HCc + n0 + x];
    __syncthreads();
#pragma unroll
    for (int j = 0; j < 4; j++)
        wt[(size_t)(n0 + y + 8 * j) * Dc + k0 + x] = f2tf32f(t[x][y + 8 * j]);
}

// ---------------- batched strip-mined tf32 GEMM ----------------
// Per z: out[M,512] = A[M,128] @ W + bias.  W pre-transposed [512][128] tf32-rounded.
// CTA: n-tile (blockIdx.x*128), strip of m-tiles (blockIdx.y + k*gridDim.y), mat z.
struct GemmJob { const float* A; const float* W; const float* bias; float* out; int tiles; };
struct GemmBatch { GemmJob j[6]; };

#define LDS_ 132
__global__ __launch_bounds__(256, 1)
void k_gemm(GemmBatch P) {
    extern __shared__ float sm[];
    const GemmJob jb = P.j[blockIdx.z];
    int tiles = jb.tiles;
    int t = blockIdx.y;
    if (t >= tiles) return;
    const int GY = gridDim.y;

    float* Bs  = sm;
    float* As0 = sm + 128 * LDS_;
    float* As1 = As0 + 128 * LDS_;
    uint32_t bsAddr   = (uint32_t)__cvta_generic_to_shared(Bs);
    uint32_t aAddr[2] = {(uint32_t)__cvta_generic_to_shared(As0),
                         (uint32_t)__cvta_generic_to_shared(As1)};

    int tid = threadIdx.x;
    int n0 = blockIdx.x * 128;

    // load B tile once (rows n0..n0+127, contiguous 64KB)
    {
        const float* Wp = jb.W + (size_t)n0 * Dc;
#pragma unroll
        for (int it = 0; it < 16; it++) {
            int idx = tid + it * 256;
            int r = idx >> 5, c4 = (idx & 31) << 2;
            uint32_t d = bsAddr + (uint32_t)((r * LDS_ + c4) * 4);
            asm volatile("cp.async.cg.shared.global [%0], [%1], 16;"
                         :: "r"(d), "l"(Wp + r * Dc + c4));
        }
    }
    auto issueA = [&](int tile, int buf) {
        const float* Ap = jb.A + (size_t)tile * 128 * Dc;
#pragma unroll
        for (int it = 0; it < 16; it++) {
            int idx = tid + it * 256;
            int r = idx >> 5, c4 = (idx & 31) << 2;
            uint32_t d = aAddr[buf] + (uint32_t)((r * LDS_ + c4) * 4);
            asm volatile("cp.async.cg.shared.global [%0], [%1], 16;"
                         :: "r"(d), "l"(Ap + r * Dc + c4));
        }
    };
    issueA(t, 0);
    asm volatile("cp.async.commit_group;" ::: "memory");
    asm volatile("cp.async.wait_group 0;" ::: "memory");
    __syncthreads();

    int lane = tid & 31, wid = tid >> 5;
    int wm = (wid & 3) * 32, wn = (wid >> 2) * 64;
    int gid = lane >> 2, tig = lane & 3;

    // per-lane ldmatrix base offsets
    uint32_t aoff[2], boff[4];
    {
        int sel = lane >> 3, r = lane & 7;
#pragma unroll
        for (int mt = 0; mt < 2; mt++)
            aoff[mt] = (uint32_t)(((wm + mt * 16 + (sel & 1) * 8 + r) * LDS_ + (sel >> 1) * 4) * 4);
#pragma unroll
        for (int p = 0; p < 4; p++)
            boff[p] = bsAddr + (uint32_t)(((wn + p * 16 + (sel >> 1) * 8 + r) * LDS_ + (sel & 1) * 4) * 4);
    }

#define LDFRAG(st, ks) do { \
    uint32_t kb = (uint32_t)((ks) * 32); \
    _Pragma("unroll") \
    for (int mt = 0; mt < 2; mt++) \
        asm volatile("ldmatrix.sync.aligned.m8n8.x4.shared.b16 {%0,%1,%2,%3}, [%4];" \
            : "=r"(af[st][mt][0]), "=r"(af[st][mt][1]), "=r"(af[st][mt][2]), "=r"(af[st][mt][3]) \
            : "r"(aCur + aoff[mt] + kb)); \
    _Pragma("unroll") \
    for (int p = 0; p < 4; p++) \
        asm volatile("ldmatrix.sync.aligned.m8n8.x4.shared.b16 {%0,%1,%2,%3}, [%4];" \
            : "=r"(bf[st][p][0]), "=r"(bf[st][p][1]), "=r"(bf[st][p][2]), "=r"(bf[st][p][3]) \
            : "r"(boff[p] + kb)); \
} while (0)

    int buf = 0;
    for (;;) {
        int tn = t + GY;
        if (tn < tiles) {
            issueA(tn, buf ^ 1);
            asm volatile("cp.async.commit_group;" ::: "memory");
        }
        uint32_t aCur = aAddr[buf];
        float acc[2][8][4];
#pragma unroll
        for (int mt = 0; mt < 2; mt++)
#pragma unroll
            for (int nt = 0; nt < 8; nt++)
#pragma unroll
                for (int q = 0; q < 4; q++) acc[mt][nt][q] = 0.f;

        uint32_t af[2][2][4], bf[2][4][4];
        LDFRAG(0, 0);
#pragma unroll
        for (int ks = 0; ks < 16; ks++) {
            int cu = ks & 1;
            if (ks < 15) LDFRAG(cu ^ 1, ks + 1);
#pragma unroll
            for (int mt = 0; mt < 2; mt++)
#pragma unroll
                for (int nt = 0; nt < 8; nt++) {
                    uint32_t b0 = (nt & 1) ? bf[cu][nt >> 1][2] : bf[cu][nt >> 1][0];
                    uint32_t b1 = (nt & 1) ? bf[cu][nt >> 1][3] : bf[cu][nt >> 1][1];
                    mma_tf32(acc[mt][nt], af[cu][mt], b0, b1);
                }
        }
        // epilogue (streaming stores to keep A in L2)
        int tm0 = t * 128;
#pragma unroll
        for (int mt = 0; mt < 2; mt++) {
            int r0 = tm0 + wm + mt * 16 + gid;
#pragma unroll
            for (int nt = 0; nt < 8; nt++) {
                int col = n0 + wn + nt * 8 + tig * 2;
                float2 bv = *(const float2*)&jb.bias[col];
                __stcs((float2*)&jb.out[(size_t)r0 * HCc + col],
                       make_float2(acc[mt][nt][0] + bv.x, acc[mt][nt][1] + bv.y));
                __stcs((float2*)&jb.out[(size_t)(r0 + 8) * HCc + col],
                       make_float2(acc[mt][nt][2] + bv.x, acc[mt][nt][3] + bv.y));
            }
        }
        if (tn >= tiles) break;
        asm volatile("cp.async.wait_group 0;" ::: "memory");
        __syncthreads();
        t = tn; buf ^= 1;
    }
#undef LDFRAG
}

// ---------------- elementwise kernels ----------------
__global__ void k_zero4(float4* __restrict__ p, int n4) {
    int i = blockIdx.x * blockDim.x + threadIdx.x;
    if (i < n4) p[i] = make_float4(0.f, 0.f, 0.f, 0.f);
}
__global__ void k_init_md(float* __restrict__ m, float* __restrict__ den, int n) {
    int i = blockIdx.x * blockDim.x + threadIdx.x;
    if (i < n) { m[i] = __int_as_float(0xff800000); den[i] = 0.f; }
}
__global__ void k_embed4(const int* __restrict__ idx, const float4* __restrict__ emb,
                         float4* __restrict__ out, int n4) {
    int i = blockIdx.x * blockDim.x + threadIdx.x;
    if (i < n4) {
        float4 v = emb[idx[i >> 5] * 32 + (i & 31)];
        v.x = f2tf32f(v.x); v.y = f2tf32f(v.y); v.z = f2tf32f(v.z); v.w = f2tf32f(v.w);
        out[i] = v;
    }
}
// cell = round_tf32(relu(acc + sum_r conv_bias[l,r,:]))
__global__ void k_relu_bias4(float4* __restrict__ cell, const float4* __restrict__ acc,
                             const float* __restrict__ cb, int n4) {
    int i = blockIdx.x * blockDim.x + threadIdx.x;
    if (i < n4) {
        int c = (i & 31) * 4;
        float4 a = acc[i];
        float4 o;
        o.x = f2tf32f(fmaxf(a.x + cb[c + 0] + cb[128 + c + 0] + cb[256 + c + 0], 0.f));
        o.y = f2tf32f(fmaxf(a.y + cb[c + 1] + cb[128 + c + 1] + cb[256 + c + 1], 0.f));
        o.z = f2tf32f(fmaxf(a.z + cb[c + 2] + cb[128 + c + 2] + cb[256 + c + 2], 0.f));
        o.w = f2tf32f(fmaxf(a.w + cb[c + 3] + cb[128 + c + 3] + cb[256 + c + 3], 0.f));
        cell[i] = o;
    }
}

// ---------------- batched edge kernels (z = relation) ----------------
struct EdgeBatch {
    const int* src[3]; const int* dst[3];
    const float* xl[3]; const float* xr[3];
    const float* att[3];
    float* sc[3]; float* m[3]; float* den[3];
    int E[3];
};

__global__ void k_score_b(EdgeBatch P) {
    int z = blockIdx.z;
    int e = blockIdx.x * (blockDim.x >> 5) + (threadIdx.x >> 5);
    int lane = threadIdx.x & 31;
    if (e >= P.E[z]) return;
    int s = P.src[z][e], d = P.dst[z][e];
    const float* xls = P.xl[z] + (size_t)s * HCc;
    const float* xrd = P.xr[z] + (size_t)d * HCc;
    const float* att = P.att[z];
    float part[4] = {0.f, 0.f, 0.f, 0.f};
#pragma unroll
    for (int k = 0; k < 16; k++) {
        int idx = lane + 32 * k;
        float v = xls[idx] + xrd[idx];
        v = v > 0.f ? v : SLOPEc * v;
        part[k >> 2] += v * att[idx];
    }
#pragma unroll
    for (int h = 0; h < 4; h++) {
        float v = part[h];
#pragma unroll
        for (int off = 16; off; off >>= 1) v += __shfl_down_sync(0xffffffffu, v, off);
        if (lane == 0) {
            P.sc[z][e * 4 + h] = v;
            atomicMaxF(&P.m[z][d * 4 + h], v);
        }
    }
}

__global__ void k_softmax_b(EdgeBatch P) {
    int z = blockIdx.z;
    int i = blockIdx.x * blockDim.x + threadIdx.x;
    if (i >= P.E[z] * 4) return;
    int e = i >> 2, h = i & 3;
    int d = P.dst[z][e];
    float p = expf(P.sc[z][i] - P.m[z][d * 4 + h]);
    P.sc[z][i] = p;
    atomicAdd(&P.den[z][d * 4 + h], p);
}

__global__ void k_aggr_b(EdgeBatch P, float* __restrict__ acc) {
    int z = blockIdx.z;
    int e = blockIdx.x * (blockDim.x >> 5) + (threadIdx.x >> 5);
    int lane = threadIdx.x & 31;
    if (e >= P.E[z]) return;
    int s = P.src[z][e], d = P.dst[z][e];
    float alpha[4];
#pragma unroll
    for (int h = 0; h < 4; h++)
        alpha[h] = P.sc[z][e * 4 + h] / (P.den[z][d * 4 + h] + 1e-16f);
    const float* xls = P.xl[z] + (size_t)s * HCc;
    float* accd = acc + (size_t)d * Dc;
#pragma unroll
    for (int j = 0; j < 4; j++) {
        int c = lane + 32 * j;
        float v = 0.f;
#pragma unroll
        for (int h = 0; h < 4; h++) v += alpha[h] * xls[h * 128 + c];
        atomicAdd(&accd[c], 0.25f * v);
    }
}

// ---------------- pooling ----------------
__global__ void k_pool_add(const float* __restrict__ cell, const int* __restrict__ batch,
                           float* __restrict__ sums, int n) {
    int i = blockIdx.x * blockDim.x + threadIdx.x;
    if (i < n) atomicAdd(&sums[batch[i >> 7] * Dc + (i & 127)], cell[i]);
}
__global__ void k_cnt(const int* __restrict__ batch, float* __restrict__ cnts, int n) {
    int i = blockIdx.x * blockDim.x + threadIdx.x;
    if (i < n) atomicAdd(&cnts[batch[i]], 1.f);
}

// ---------------- heads ----------------
__global__ void k_head(const float* __restrict__ sums, const float* __restrict__ cnts,
                       const float* __restrict__ fc1W, const float* __restrict__ fc1b,
                       const float* __restrict__ polW, const float* __restrict__ polb,
                       const float* __restrict__ valW, const float* __restrict__ valb,
                       float* __restrict__ out_policy, float* __restrict__ out_value) {
    int b = blockIdx.x;
    int t = threadIdx.x;  // 64
    __shared__ float pooled[128];
    __shared__ float hsh[64];
    float cnt = fmaxf(cnts[b], 1.f);
    pooled[t]      = sums[b * Dc + t] / cnt;
    pooled[t + 64] = sums[b * Dc + 64 + t] / cnt;
    __syncthreads();
    float a = fc1b[t];
#pragma unroll 4
    for (int d = 0; d < 128; d++) a += pooled[d] * fc1W[d * 64 + t];
    hsh[t] = fmaxf(a, 0.f);
    __syncthreads();
    if (t < BWc) {
        float a2 = polb[t];
#pragma unroll 4
        for (int k = 0; k < 64; k++) a2 += hsh[k] * polW[k * BWc + t];
        out_policy[b * BWc + t] = a2;
    }
    if (t == 8) {
        float a2 = valb[0];
#pragma unroll 4
        for (int k = 0; k < 64; k++) a2 += hsh[k] * valW[k];
        out_value[b] = tanhf(a2);
    }
}

// ---------------- launch ----------------
extern "C" void kernel_launch(void* const* d_in, const int* in_sizes, int n_in,
                              void* d_out, int out_size) {
    const int* cell_x     = (const int*)d_in[0];
    const int* piece_x    = (const int*)d_in[1];
    const int* srcs[3]    = {(const int*)d_in[2], (const int*)d_in[4], (const int*)d_in[6]};
    const int* dsts[3]    = {(const int*)d_in[3], (const int*)d_in[5], (const int*)d_in[7]};
    const int  Es[3]      = {in_sizes[2], in_sizes[4], in_sizes[6]};
    const int* cell_batch = (const int*)d_in[8];
    const float* cell_emb  = (const float*)d_in[9];
    const float* piece_emb = (const float*)d_in[10];
    const float* Wl  = (const float*)d_in[11];
    const float* bl  = (const float*)d_in[12];
    const float* Wr  = (const float*)d_in[13];
    const float* br  = (const float*)d_in[14];
    const float* att = (const float*)d_in[15];
    const float* cb  = (const float*)d_in[16];
    const float* fc1W = (const float*)d_in[17];
    const float* fc1b = (const float*)d_in[18];
    const float* polW = (const float*)d_in[19];
    const float* polb = (const float*)d_in[20];
    const float* valW = (const float*)d_in[21];
    const float* valb = (const float*)d_in[22];

    const int NC = in_sizes[0];
    const int NP = in_sizes[1];

    float *p_cell, *p_acc, *p_piece, *p_sums, *p_cnts, *p_wt;
    float *p_xl[3], *p_xr[3], *p_sc, *p_m, *p_den;
    cudaGetSymbolAddress((void**)&p_cell,  g_cell);
    cudaGetSymbolAddress((void**)&p_acc,   g_acc);
    cudaGetSymbolAddress((void**)&p_piece, g_piece);
    cudaGetSymbolAddress((void**)&p_xl[0], g_xl0);
    cudaGetSymbolAddress((void**)&p_xl[1], g_xl1);
    cudaGetSymbolAddress((void**)&p_xl[2], g_xl2);
    cudaGetSymbolAddress((void**)&p_xr[0], g_xr0);
    cudaGetSymbolAddress((void**)&p_xr[1], g_xr1);
    cudaGetSymbolAddress((void**)&p_xr[2], g_xr2);
    cudaGetSymbolAddress((void**)&p_sc,    g_sc);
    cudaGetSymbolAddress((void**)&p_m,     g_m);
    cudaGetSymbolAddress((void**)&p_den,   g_den);
    cudaGetSymbolAddress((void**)&p_sums,  g_sums);
    cudaGetSymbolAddress((void**)&p_cnts,  g_cnts);
    cudaGetSymbolAddress((void**)&p_wt,    g_wt);

    const int SMEM_GEMM = 3 * 128 * LDS_ * 4;  // 202752 B
    cudaFuncSetAttribute(k_gemm, cudaFuncAttributeMaxDynamicSharedMemorySize, SMEM_GEMM);

    const int T = 256;
    const size_t MATSZ = (size_t)Dc * HCc;  // 65536

    // prep: round+transpose all 24 weight matrices
    k_wprep<<<dim3(16, 4, 12), dim3(32, 8)>>>(Wl, p_wt);
    k_wprep<<<dim3(16, 4, 12), dim3(32, 8)>>>(Wr, p_wt + 12 * MATSZ);

    // initial embeddings (tf32-rounded)
    k_embed4<<<(NC * 32 + T - 1) / T, T>>>(cell_x, (const float4*)cell_emb, (float4*)p_cell, NC * 32);
    k_embed4<<<(NP * 32 + T - 1) / T, T>>>(piece_x, (const float4*)piece_emb, (float4*)p_piece, NP * 32);

    for (int l = 0; l < Lc; l++) {
        k_zero4<<<(NC * 32 + T - 1) / T, T>>>((float4*)p_acc, NC * 32);

        GemmBatch gb;
        // z0: piece @ Wl[l,0] -> xl0 ; z1: cell @ Wr[l,0] -> xr0 ;
        // z2: cell @ Wl[l,1] -> xl1 ; z3: cell @ Wr[l,1] -> xr1 ;
        // z4: cell @ Wl[l,2] -> xl2 ; z5: cell @ Wr[l,2] -> xr2
        for (int z = 0; z < 6; z++) {
            int r = (z == 0 || z == 1) ? 0 : (z <= 3 ? 1 : 2);
            bool isL = (z == 0) || (z == 2) || (z == 4);
            int mat = l * 3 + r;
            gb.j[z].A     = (z == 0) ? p_piece : p_cell;
            gb.j[z].W     = p_wt + (isL ? mat : 12 + mat) * MATSZ;
            gb.j[z].bias  = (isL ? bl : br) + (size_t)mat * HCc;
            gb.j[z].out   = isL ? p_xl[r] : p_xr[r];
            gb.j[z].tiles = ((z == 0) ? NP : NC) / 128;
        }
        k_gemm<<<dim3(4, 37, 6), 256, SMEM_GEMM>>>(gb);

        k_init_md<<<(3 * NC * Hc + T - 1) / T, T>>>(p_m, p_den, 3 * NC * Hc);

        EdgeBatch eb;
        int Emax = 0;
        for (int r = 0; r < 3; r++) {
            eb.src[r] = srcs[r]; eb.dst[r] = dsts[r];
            eb.xl[r] = p_xl[r]; eb.xr[r] = p_xr[r];
            eb.att[r] = att + (size_t)(l * 3 + r) * HCc;
            eb.sc[r]  = p_sc  + (size_t)r * NCc * Hc;
            eb.m[r]   = p_m   + (size_t)r * NCc * Hc;
            eb.den[r] = p_den + (size_t)r * NCc * Hc;
            eb.E[r] = Es[r];
            if (Es[r] > Emax) Emax = Es[r];
        }
        int wpb = T / 32;
        k_score_b  <<<dim3((Emax + wpb - 1) / wpb, 1, 3), T>>>(eb);
        k_softmax_b<<<dim3((Emax * 4 + T - 1) / T, 1, 3), T>>>(eb);
        k_aggr_b   <<<dim3((Emax + wpb - 1) / wpb, 1, 3), T>>>(eb, p_acc);

        k_relu_bias4<<<(NC * 32 + T - 1) / T, T>>>(
            (float4*)p_cell, (const float4*)p_acc, cb + (size_t)l * 3 * Cc, NC * 32);
    }

    // global mean pool
    k_zero4<<<(Bc * 32 + T - 1) / T, T>>>((float4*)p_sums, Bc * 32);
    k_zero4<<<(Bc / 4 + T - 1) / T, T>>>((float4*)p_cnts, Bc / 4);
    k_pool_add<<<(NC * Dc + T - 1) / T, T>>>(p_cell, cell_batch, p_sums, NC * Dc);
    k_cnt<<<(NC + T - 1) / T, T>>>(cell_batch, p_cnts, NC);

    // heads
    float* out = (float*)d_out;
    k_head<<<Bc, 64>>>(p_sums, p_cnts, fc1W, fc1b, polW, polb, valW, valb,
                       out, out + (size_t)Bc * BWc);
}

// round 5
// speedup vs baseline: 3.2750x; 1.2219x over previous
#include <cuda_runtime.h>
#include <cuda_fp16.h>
#include <cstdint>
#include <math.h>

// Problem constants
#define NCc 65536
#define NPc 32768
#define Dc  128
#define Hc  4
#define Cc  128
#define HCc 512
#define Bc  1024
#define Lc  4
#define BWc 7
#define SLOPEc 0.2f

// ---------------- scratch (device globals) ----------------
__device__ float  g_cell [NCc * Dc];
__device__ float  g_acc  [NCc * Dc];
__device__ float  g_piece[NPc * Dc];
__device__ __half g_xl0  [NPc * HCc];
__device__ __half g_xl1  [NCc * HCc];
__device__ __half g_xl2  [NCc * HCc];
__device__ __half g_xr0  [NCc * HCc];
__device__ __half g_xr1  [NCc * HCc];
__device__ __half g_xr2  [NCc * HCc];
__device__ float  g_sc   [3][NCc * Hc];
__device__ float  g_m    [3][NCc * Hc];
__device__ float  g_den  [3][NCc * Hc];
__device__ float  g_sums [Bc * Dc];
__device__ float  g_cnts [Bc];
__device__ float  g_wt   [24 * HCc * Dc];   // tf32-rounded, transposed weights [mat][n=512][k=128]

// ---------------- helpers ----------------
__device__ __forceinline__ void atomicMaxF(float* addr, float value) {
    if (value >= 0.f) atomicMax((int*)addr, __float_as_int(value));
    else              atomicMin((unsigned int*)addr, __float_as_uint(value));
}
__device__ __forceinline__ float f2tf32f(float x) {
    uint32_t r;
    asm("cvt.rna.tf32.f32 %0, %1;" : "=r"(r) : "f"(x));
    return __uint_as_float(r);
}
__device__ __forceinline__ void mma_tf32(float* c, const uint32_t* a, uint32_t b0, uint32_t b1) {
    asm volatile(
        "mma.sync.aligned.m16n8k8.row.col.f32.tf32.tf32.f32 "
        "{%0,%1,%2,%3}, {%4,%5,%6,%7}, {%8,%9}, {%0,%1,%2,%3};"
        : "+f"(c[0]), "+f"(c[1]), "+f"(c[2]), "+f"(c[3])
        : "r"(a[0]), "r"(a[1]), "r"(a[2]), "r"(a[3]), "r"(b0), "r"(b1));
}

// ---------------- weight prep: tf32-round + transpose [k][n] -> [n][k] ----------------
__global__ void k_wprep(const float* __restrict__ W, float* __restrict__ WT) {
    __shared__ float t[32][33];
    int mat = blockIdx.z;
    int n0 = blockIdx.x * 32, k0 = blockIdx.y * 32;
    int x = threadIdx.x, y = threadIdx.y;
    const float* w  = W  + (size_t)mat * Dc * HCc;
    float*       wt = WT + (size_t)mat * Dc * HCc;
#pragma unroll
    for (int j = 0; j < 4; j++)
        t[y + 8 * j][x] = w[(size_t)(k0 + y + 8 * j) * HCc + n0 + x];
    __syncthreads();
#pragma unroll
    for (int j = 0; j < 4; j++)
        wt[(size_t)(n0 + y + 8 * j) * Dc + k0 + x] = f2tf32f(t[x][y + 8 * j]);
}

// ---------------- batched strip-mined tf32 GEMM (512 threads, fp16 out) ----------------
struct GemmJob { const float* A; const float* W; const float* bias; __half* out; int tiles; };
struct GemmBatch { GemmJob j[6]; };

#define LDS_ 132
__global__ __launch_bounds__(512, 1)
void k_gemm(GemmBatch P) {
    extern __shared__ float sm[];
    const GemmJob jb = P.j[blockIdx.z];
    int tiles = jb.tiles;
    int t = blockIdx.y;
    if (t >= tiles) return;
    const int GY = gridDim.y;

    float* Bs  = sm;
    float* As0 = sm + 128 * LDS_;
    float* As1 = As0 + 128 * LDS_;
    uint32_t bsAddr   = (uint32_t)__cvta_generic_to_shared(Bs);
    uint32_t aAddr[2] = {(uint32_t)__cvta_generic_to_shared(As0),
                         (uint32_t)__cvta_generic_to_shared(As1)};

    int tid = threadIdx.x;
    int n0 = blockIdx.x * 128;

    // load B tile once
    {
        const float* Wp = jb.W + (size_t)n0 * Dc;
#pragma unroll
        for (int it = 0; it < 8; it++) {
            int idx = tid + it * 512;
            int r = idx >> 5, c4 = (idx & 31) << 2;
            uint32_t d = bsAddr + (uint32_t)((r * LDS_ + c4) * 4);
            asm volatile("cp.async.cg.shared.global [%0], [%1], 16;"
                         :: "r"(d), "l"(Wp + r * Dc + c4));
        }
    }
    auto issueA = [&](int tile, int buf) {
        const float* Ap = jb.A + (size_t)tile * 128 * Dc;
#pragma unroll
        for (int it = 0; it < 8; it++) {
            int idx = tid + it * 512;
            int r = idx >> 5, c4 = (idx & 31) << 2;
            uint32_t d = aAddr[buf] + (uint32_t)((r * LDS_ + c4) * 4);
            asm volatile("cp.async.cg.shared.global [%0], [%1], 16;"
                         :: "r"(d), "l"(Ap + r * Dc + c4));
        }
    };
    issueA(t, 0);
    asm volatile("cp.async.commit_group;" ::: "memory");
    asm volatile("cp.async.wait_group 0;" ::: "memory");
    __syncthreads();

    int lane = tid & 31, wid = tid >> 5;
    int wm = (wid & 3) * 32, wn = (wid >> 2) * 32;   // 4x4 warps, warp tile 32x32
    int gid = lane >> 2, tig = lane & 3;

    uint32_t aoff[2], boff[2];
    {
        int sel = lane >> 3, r = lane & 7;
#pragma unroll
        for (int mt = 0; mt < 2; mt++)
            aoff[mt] = (uint32_t)(((wm + mt * 16 + (sel & 1) * 8 + r) * LDS_ + (sel >> 1) * 4) * 4);
#pragma unroll
        for (int p = 0; p < 2; p++)
            boff[p] = bsAddr + (uint32_t)(((wn + p * 16 + (sel >> 1) * 8 + r) * LDS_ + (sel & 1) * 4) * 4);
    }

#define LDFRAG(st, ks) do { \
    uint32_t kb = (uint32_t)((ks) * 32); \
    _Pragma("unroll") \
    for (int mt = 0; mt < 2; mt++) \
        asm volatile("ldmatrix.sync.aligned.m8n8.x4.shared.b16 {%0,%1,%2,%3}, [%4];" \
            : "=r"(af[st][mt][0]), "=r"(af[st][mt][1]), "=r"(af[st][mt][2]), "=r"(af[st][mt][3]) \
            : "r"(aCur + aoff[mt] + kb)); \
    _Pragma("unroll") \
    for (int p = 0; p < 2; p++) \
        asm volatile("ldmatrix.sync.aligned.m8n8.x4.shared.b16 {%0,%1,%2,%3}, [%4];" \
            : "=r"(bf[st][p][0]), "=r"(bf[st][p][1]), "=r"(bf[st][p][2]), "=r"(bf[st][p][3]) \
            : "r"(boff[p] + kb)); \
} while (0)

    int buf = 0;
    for (;;) {
        int tn = t + GY;
        if (tn < tiles) {
            issueA(tn, buf ^ 1);
            asm volatile("cp.async.commit_group;" ::: "memory");
        }
        uint32_t aCur = aAddr[buf];
        float acc[2][4][4];
#pragma unroll
        for (int mt = 0; mt < 2; mt++)
#pragma unroll
            for (int nt = 0; nt < 4; nt++)
#pragma unroll
                for (int q = 0; q < 4; q++) acc[mt][nt][q] = 0.f;

        uint32_t af[2][2][4], bf[2][2][4];
        LDFRAG(0, 0);
#pragma unroll
        for (int ks = 0; ks < 16; ks++) {
            int cu = ks & 1;
            if (ks < 15) LDFRAG(cu ^ 1, ks + 1);
#pragma unroll
            for (int mt = 0; mt < 2; mt++)
#pragma unroll
                for (int nt = 0; nt < 4; nt++) {
                    int p = nt >> 1;
                    uint32_t b0 = bf[cu][p][(nt & 1) * 2];
                    uint32_t b1 = bf[cu][p][(nt & 1) * 2 + 1];
                    mma_tf32(acc[mt][nt], af[cu][mt], b0, b1);
                }
        }
        // epilogue: bias add + fp16 convert, streaming stores
        int tm0 = t * 128;
#pragma unroll
        for (int mt = 0; mt < 2; mt++) {
            int r0 = tm0 + wm + mt * 16 + gid;
#pragma unroll
            for (int nt = 0; nt < 4; nt++) {
                int col = n0 + wn + nt * 8 + tig * 2;
                float2 bv = *(const float2*)&jb.bias[col];
                __half2 h0 = __floats2half2_rn(acc[mt][nt][0] + bv.x, acc[mt][nt][1] + bv.y);
                __half2 h1 = __floats2half2_rn(acc[mt][nt][2] + bv.x, acc[mt][nt][3] + bv.y);
                __stcs((unsigned int*)&jb.out[(size_t)r0 * HCc + col],
                       *(unsigned int*)&h0);
                __stcs((unsigned int*)&jb.out[(size_t)(r0 + 8) * HCc + col],
                       *(unsigned int*)&h1);
            }
        }
        if (tn >= tiles) break;
        asm volatile("cp.async.wait_group 0;" ::: "memory");
        __syncthreads();
        t = tn; buf ^= 1;
    }
#undef LDFRAG
}

// ---------------- elementwise kernels ----------------
__global__ void k_zero4(float4* __restrict__ p, int n4) {
    int i = blockIdx.x * blockDim.x + threadIdx.x;
    if (i < n4) p[i] = make_float4(0.f, 0.f, 0.f, 0.f);
}
__global__ void k_init_md(float* __restrict__ m, float* __restrict__ den, int n) {
    int i = blockIdx.x * blockDim.x + threadIdx.x;
    if (i < n) { m[i] = __int_as_float(0xff800000); den[i] = 0.f; }
}
__global__ void k_embed4(const int* __restrict__ idx, const float4* __restrict__ emb,
                         float4* __restrict__ out, int n4) {
    int i = blockIdx.x * blockDim.x + threadIdx.x;
    if (i < n4) {
        float4 v = emb[idx[i >> 5] * 32 + (i & 31)];
        v.x = f2tf32f(v.x); v.y = f2tf32f(v.y); v.z = f2tf32f(v.z); v.w = f2tf32f(v.w);
        out[i] = v;
    }
}
__global__ void k_relu_bias4(float4* __restrict__ cell, const float4* __restrict__ acc,
                             const float* __restrict__ cb, int n4) {
    int i = blockIdx.x * blockDim.x + threadIdx.x;
    if (i < n4) {
        int c = (i & 31) * 4;
        float4 a = acc[i];
        float4 o;
        o.x = f2tf32f(fmaxf(a.x + cb[c + 0] + cb[128 + c + 0] + cb[256 + c + 0], 0.f));
        o.y = f2tf32f(fmaxf(a.y + cb[c + 1] + cb[128 + c + 1] + cb[256 + c + 1], 0.f));
        o.z = f2tf32f(fmaxf(a.z + cb[c + 2] + cb[128 + c + 2] + cb[256 + c + 2], 0.f));
        o.w = f2tf32f(fmaxf(a.w + cb[c + 3] + cb[128 + c + 3] + cb[256 + c + 3], 0.f));
        cell[i] = o;
    }
}

// ---------------- batched edge kernels (z = relation, fp16 features) ----------------
struct EdgeBatch {
    const int* src[3]; const int* dst[3];
    const __half* xl[3]; const __half* xr[3];
    const float* att[3];
    float* sc[3]; float* m[3]; float* den[3];
    int E[3];
};

__global__ void k_score_b(EdgeBatch P) {
    int z = blockIdx.z;
    int e = blockIdx.x * (blockDim.x >> 5) + (threadIdx.x >> 5);
    int lane = threadIdx.x & 31;
    if (e >= P.E[z]) return;
    int s = P.src[z][e], d = P.dst[z][e];
    const __half2* xls = (const __half2*)P.xl[z] + (size_t)s * 256;
    const __half2* xrd = (const __half2*)P.xr[z] + (size_t)d * 256;
    const float* att = P.att[z];
    float part[4] = {0.f, 0.f, 0.f, 0.f};
#pragma unroll
    for (int h = 0; h < 4; h++)
#pragma unroll
        for (int k = 0; k < 2; k++) {
            int idx = h * 64 + k * 32 + lane;
            float2 a2 = __half22float2(xls[idx]);
            float2 b2 = __half22float2(xrd[idx]);
            float vx = a2.x + b2.x, vy = a2.y + b2.y;
            vx = vx > 0.f ? vx : SLOPEc * vx;
            vy = vy > 0.f ? vy : SLOPEc * vy;
            float2 at = *(const float2*)&att[2 * idx];
            part[h] += vx * at.x + vy * at.y;
        }
#pragma unroll
    for (int h = 0; h < 4; h++) {
        float v = part[h];
#pragma unroll
        for (int off = 16; off; off >>= 1) v += __shfl_down_sync(0xffffffffu, v, off);
        if (lane == 0) {
            P.sc[z][e * 4 + h] = v;
            atomicMaxF(&P.m[z][d * 4 + h], v);
        }
    }
}

__global__ void k_softmax_b(EdgeBatch P) {
    int z = blockIdx.z;
    int i = blockIdx.x * blockDim.x + threadIdx.x;
    if (i >= P.E[z] * 4) return;
    int e = i >> 2, h = i & 3;
    int d = P.dst[z][e];
    float p = expf(P.sc[z][i] - P.m[z][d * 4 + h]);
    P.sc[z][i] = p;
    atomicAdd(&P.den[z][d * 4 + h], p);
}

__global__ void k_aggr_b(EdgeBatch P, float* __restrict__ acc) {
    int z = blockIdx.z;
    int e = blockIdx.x * (blockDim.x >> 5) + (threadIdx.x >> 5);
    int lane = threadIdx.x & 31;
    if (e >= P.E[z]) return;
    int s = P.src[z][e], d = P.dst[z][e];
    float alpha[4];
#pragma unroll
    for (int h = 0; h < 4; h++)
        alpha[h] = P.sc[z][e * 4 + h] / (P.den[z][d * 4 + h] + 1e-16f);
    const __half2* xls = (const __half2*)P.xl[z] + (size_t)s * 256;
    float* accd = acc + (size_t)d * Dc;
#pragma unroll
    for (int j = 0; j < 2; j++) {
        int cc = lane + 32 * j;             // half2 index within head block of 64
        float vx = 0.f, vy = 0.f;
#pragma unroll
        for (int h = 0; h < 4; h++) {
            float2 x = __half22float2(xls[h * 64 + cc]);
            vx += alpha[h] * x.x;
            vy += alpha[h] * x.y;
        }
        atomicAdd(&accd[2 * cc],     0.25f * vx);
        atomicAdd(&accd[2 * cc + 1], 0.25f * vy);
    }
}

// ---------------- pooling ----------------
__global__ void k_pool_add(const float* __restrict__ cell, const int* __restrict__ batch,
                           float* __restrict__ sums, int n) {
    int i = blockIdx.x * blockDim.x + threadIdx.x;
    if (i < n) atomicAdd(&sums[batch[i >> 7] * Dc + (i & 127)], cell[i]);
}
__global__ void k_cnt(const int* __restrict__ batch, float* __restrict__ cnts, int n) {
    int i = blockIdx.x * blockDim.x + threadIdx.x;
    if (i < n) atomicAdd(&cnts[batch[i]], 1.f);
}

// ---------------- heads ----------------
__global__ void k_head(const float* __restrict__ sums, const float* __restrict__ cnts,
                       const float* __restrict__ fc1W, const float* __restrict__ fc1b,
                       const float* __restrict__ polW, const float* __restrict__ polb,
                       const float* __restrict__ valW, const float* __restrict__ valb,
                       float* __restrict__ out_policy, float* __restrict__ out_value) {
    int b = blockIdx.x;
    int t = threadIdx.x;  // 64
    __shared__ float pooled[128];
    __shared__ float hsh[64];
    float cnt = fmaxf(cnts[b], 1.f);
    pooled[t]      = sums[b * Dc + t] / cnt;
    pooled[t + 64] = sums[b * Dc + 64 + t] / cnt;
    __syncthreads();
    float a = fc1b[t];
#pragma unroll 4
    for (int d = 0; d < 128; d++) a += pooled[d] * fc1W[d * 64 + t];
    hsh[t] = fmaxf(a, 0.f);
    __syncthreads();
    if (t < BWc) {
        float a2 = polb[t];
#pragma unroll 4
        for (int k = 0; k < 64; k++) a2 += hsh[k] * polW[k * BWc + t];
        out_policy[b * BWc + t] = a2;
    }
    if (t == 8) {
        float a2 = valb[0];
#pragma unroll 4
        for (int k = 0; k < 64; k++) a2 += hsh[k] * valW[k];
        out_value[b] = tanhf(a2);
    }
}

// ---------------- launch ----------------
extern "C" void kernel_launch(void* const* d_in, const int* in_sizes, int n_in,
                              void* d_out, int out_size) {
    const int* cell_x     = (const int*)d_in[0];
    const int* piece_x    = (const int*)d_in[1];
    const int* srcs[3]    = {(const int*)d_in[2], (const int*)d_in[4], (const int*)d_in[6]};
    const int* dsts[3]    = {(const int*)d_in[3], (const int*)d_in[5], (const int*)d_in[7]};
    const int  Es[3]      = {in_sizes[2], in_sizes[4], in_sizes[6]};
    const int* cell_batch = (const int*)d_in[8];
    const float* cell_emb  = (const float*)d_in[9];
    const float* piece_emb = (const float*)d_in[10];
    const float* Wl  = (const float*)d_in[11];
    const float* bl  = (const float*)d_in[12];
    const float* Wr  = (const float*)d_in[13];
    const float* br  = (const float*)d_in[14];
    const float* att = (const float*)d_in[15];
    const float* cb  = (const float*)d_in[16];
    const float* fc1W = (const float*)d_in[17];
    const float* fc1b = (const float*)d_in[18];
    const float* polW = (const float*)d_in[19];
    const float* polb = (const float*)d_in[20];
    const float* valW = (const float*)d_in[21];
    const float* valb = (const float*)d_in[22];

    const int NC = in_sizes[0];
    const int NP = in_sizes[1];

    float *p_cell, *p_acc, *p_piece, *p_sums, *p_cnts, *p_wt;
    float *p_sc, *p_m, *p_den;
    __half *p_xl[3], *p_xr[3];
    cudaGetSymbolAddress((void**)&p_cell,  g_cell);
    cudaGetSymbolAddress((void**)&p_acc,   g_acc);
    cudaGetSymbolAddress((void**)&p_piece, g_piece);
    cudaGetSymbolAddress((void**)&p_xl[0], g_xl0);
    cudaGetSymbolAddress((void**)&p_xl[1], g_xl1);
    cudaGetSymbolAddress((void**)&p_xl[2], g_xl2);
    cudaGetSymbolAddress((void**)&p_xr[0], g_xr0);
    cudaGetSymbolAddress((void**)&p_xr[1], g_xr1);
    cudaGetSymbolAddress((void**)&p_xr[2], g_xr2);
    cudaGetSymbolAddress((void**)&p_sc,    g_sc);
    cudaGetSymbolAddress((void**)&p_m,     g_m);
    cudaGetSymbolAddress((void**)&p_den,   g_den);
    cudaGetSymbolAddress((void**)&p_sums,  g_sums);
    cudaGetSymbolAddress((void**)&p_cnts,  g_cnts);
    cudaGetSymbolAddress((void**)&p_wt,    g_wt);

    const int SMEM_GEMM = 3 * 128 * LDS_ * 4;  // 202752 B
    cudaFuncSetAttribute(k_gemm, cudaFuncAttributeMaxDynamicSharedMemorySize, SMEM_GEMM);

    const int T = 256;
    const size_t MATSZ = (size_t)Dc * HCc;

    k_wprep<<<dim3(16, 4, 12), dim3(32, 8)>>>(Wl, p_wt);
    k_wprep<<<dim3(16, 4, 12), dim3(32, 8)>>>(Wr, p_wt + 12 * MATSZ);

    k_embed4<<<(NC * 32 + T - 1) / T, T>>>(cell_x, (const float4*)cell_emb, (float4*)p_cell, NC * 32);
    k_embed4<<<(NP * 32 + T - 1) / T, T>>>(piece_x, (const float4*)piece_emb, (float4*)p_piece, NP * 32);

    for (int l = 0; l < Lc; l++) {
        k_zero4<<<(NC * 32 + T - 1) / T, T>>>((float4*)p_acc, NC * 32);

        GemmBatch gb;
        for (int z = 0; z < 6; z++) {
            int r = (z == 0 || z == 1) ? 0 : (z <= 3 ? 1 : 2);
            bool isL = (z == 0) || (z == 2) || (z == 4);
            int mat = l * 3 + r;
            gb.j[z].A     = (z == 0) ? p_piece : p_cell;
            gb.j[z].W     = p_wt + (isL ? mat : 12 + mat) * MATSZ;
            gb.j[z].bias  = (isL ? bl : br) + (size_t)mat * HCc;
            gb.j[z].out   = isL ? p_xl[r] : p_xr[r];
            gb.j[z].tiles = ((z == 0) ? NP : NC) / 128;
        }
        k_gemm<<<dim3(4, 37, 6), 512, SMEM_GEMM>>>(gb);

        k_init_md<<<(3 * NC * Hc + T - 1) / T, T>>>(p_m, p_den, 3 * NC * Hc);

        EdgeBatch eb;
        int Emax = 0;
        for (int r = 0; r < 3; r++) {
            eb.src[r] = srcs[r]; eb.dst[r] = dsts[r];
            eb.xl[r] = p_xl[r]; eb.xr[r] = p_xr[r];
            eb.att[r] = att + (size_t)(l * 3 + r) * HCc;
            eb.sc[r]  = p_sc  + (size_t)r * NCc * Hc;
            eb.m[r]   = p_m   + (size_t)r * NCc * Hc;
            eb.den[r] = p_den + (size_t)r * NCc * Hc;
            eb.E[r] = Es[r];
            if (Es[r] > Emax) Emax = Es[r];
        }
        int wpb = T / 32;
        k_score_b  <<<dim3((Emax + wpb - 1) / wpb, 1, 3), T>>>(eb);
        k_softmax_b<<<dim3((Emax * 4 + T - 1) / T, 1, 3), T>>>(eb);
        k_aggr_b   <<<dim3((Emax + wpb - 1) / wpb, 1, 3), T>>>(eb, p_acc);

        k_relu_bias4<<<(NC * 32 + T - 1) / T, T>>>(
            (float4*)p_cell, (const float4*)p_acc, cb + (size_t)l * 3 * Cc, NC * 32);
    }

    // global mean pool
    k_zero4<<<(Bc * 32 + T - 1) / T, T>>>((float4*)p_sums, Bc * 32);
    k_zero4<<<(Bc / 4 + T - 1) / T, T>>>((float4*)p_cnts, Bc / 4);
    k_pool_add<<<(NC * Dc + T - 1) / T, T>>>(p_cell, cell_batch, p_sums, NC * Dc);
    k_cnt<<<(NC + T - 1) / T, T>>>(cell_batch, p_cnts, NC);

    // heads
    float* out = (float*)d_out;
    k_head<<<Bc, 64>>>(p_sums, p_cnts, fc1W, fc1b, polW, polb, valW, valb,
                       out, out + (size_t)Bc * BWc);
}

// round 6
// speedup vs baseline: 4.6707x; 1.4262x over previous
#include <cuda_runtime.h>
#include <cuda_fp16.h>
#include <cstdint>
#include <math.h>

// Problem constants
#define NCc 65536
#define NPc 32768
#define Dc  128
#define Hc  4
#define Cc  128
#define HCc 512
#define Bc  1024
#define Lc  4
#define BWc 7
#define SLOPEc 0.2f

// ---------------- scratch (device globals) ----------------
__device__ __half g_cell [NCc * Dc];
__device__ float  g_acc  [NCc * Dc];
__device__ __half g_piece[NPc * Dc];
__device__ __half g_xl0  [NPc * HCc];
__device__ __half g_xl1  [NCc * HCc];
__device__ __half g_xl2  [NCc * HCc];
__device__ __half g_xr0  [NCc * HCc];
__device__ __half g_xr1  [NCc * HCc];
__device__ __half g_xr2  [NCc * HCc];
__device__ float  g_sc   [3][NCc * Hc];
__device__ float  g_m    [3][NCc * Hc];
__device__ float  g_den  [3][NCc * Hc];
__device__ float  g_sums [Bc * Dc];
__device__ float  g_cnts [Bc];
__device__ __half g_wt   [24 * HCc * Dc];   // fp16 transposed weights [mat][n=512][k=128]

// ---------------- helpers ----------------
__device__ __forceinline__ void atomicMaxF(float* addr, float value) {
    if (value >= 0.f) atomicMax((int*)addr, __float_as_int(value));
    else              atomicMin((unsigned int*)addr, __float_as_uint(value));
}
__device__ __forceinline__ void mma_f16(float* c, const uint32_t* a, uint32_t b0, uint32_t b1) {
    asm volatile(
        "mma.sync.aligned.m16n8k16.row.col.f32.f16.f16.f32 "
        "{%0,%1,%2,%3}, {%4,%5,%6,%7}, {%8,%9}, {%0,%1,%2,%3};"
        : "+f"(c[0]), "+f"(c[1]), "+f"(c[2]), "+f"(c[3])
        : "r"(a[0]), "r"(a[1]), "r"(a[2]), "r"(a[3]), "r"(b0), "r"(b1));
}

// ---------------- weight prep: fp32 [k][n] -> fp16 [n][k] ----------------
__global__ void k_wprep(const float* __restrict__ W, __half* __restrict__ WT) {
    __shared__ float t[32][33];
    int mat = blockIdx.z;
    int n0 = blockIdx.x * 32, k0 = blockIdx.y * 32;
    int x = threadIdx.x, y = threadIdx.y;
    const float* w  = W  + (size_t)mat * Dc * HCc;
    __half*      wt = WT + (size_t)mat * Dc * HCc;
#pragma unroll
    for (int j = 0; j < 4; j++)
        t[y + 8 * j][x] = w[(size_t)(k0 + y + 8 * j) * HCc + n0 + x];
    __syncthreads();
#pragma unroll
    for (int j = 0; j < 4; j++)
        wt[(size_t)(n0 + y + 8 * j) * Dc + k0 + x] = __float2half_rn(t[x][y + 8 * j]);
}

// ---------------- batched strip-mined fp16 GEMM (512 threads) ----------------
struct GemmJob { const __half* A; const __half* W; const float* bias; __half* out; int tiles; };
struct GemmBatch { GemmJob j[6]; };

#define LDH 136   // half stride per smem row (272 B)
__global__ __launch_bounds__(512, 1)
void k_gemm(GemmBatch P) {
    extern __shared__ __half smh[];
    const GemmJob jb = P.j[blockIdx.z];
    int tiles = jb.tiles;
    int t = blockIdx.y;
    if (t >= tiles) return;
    const int GY = gridDim.y;

    __half* Bs  = smh;
    __half* As0 = smh + 128 * LDH;
    __half* As1 = As0 + 128 * LDH;
    uint32_t bsAddr   = (uint32_t)__cvta_generic_to_shared(Bs);
    uint32_t aAddr[2] = {(uint32_t)__cvta_generic_to_shared(As0),
                         (uint32_t)__cvta_generic_to_shared(As1)};

    int tid = threadIdx.x;
    int n0 = blockIdx.x * 128;

    // B tile once: 128 rows x 256B; 2048 16B chunks
    {
        const __half* Wp = jb.W + (size_t)n0 * Dc;
#pragma unroll
        for (int it = 0; it < 4; it++) {
            int idx = tid + it * 512;
            int r = idx >> 4, ch = idx & 15;
            uint32_t d = bsAddr + (uint32_t)((r * LDH + ch * 8) * 2);
            asm volatile("cp.async.cg.shared.global [%0], [%1], 16;"
                         :: "r"(d), "l"(Wp + r * Dc + ch * 8));
        }
    }
    auto issueA = [&](int tile, int buf) {
        const __half* Ap = jb.A + (size_t)tile * 128 * Dc;
#pragma unroll
        for (int it = 0; it < 4; it++) {
            int idx = tid + it * 512;
            int r = idx >> 4, ch = idx & 15;
            uint32_t d = aAddr[buf] + (uint32_t)((r * LDH + ch * 8) * 2);
            asm volatile("cp.async.cg.shared.global [%0], [%1], 16;"
                         :: "r"(d), "l"(Ap + r * Dc + ch * 8));
        }
    };
    issueA(t, 0);
    asm volatile("cp.async.commit_group;" ::: "memory");
    asm volatile("cp.async.wait_group 0;" ::: "memory");
    __syncthreads();

    int lane = tid & 31, wid = tid >> 5;
    int wm = (wid & 3) * 32, wn = (wid >> 2) * 32;   // 4x4 warps, warp tile 32x32
    int gid = lane >> 2, tig = lane & 3;

    // ldmatrix byte offsets
    uint32_t aoff[2], boff[2];
#pragma unroll
    for (int mt = 0; mt < 2; mt++)
        aoff[mt] = (uint32_t)(((wm + mt * 16 + (lane & 15)) * LDH + (lane >> 4) * 8) * 2);
#pragma unroll
    for (int p = 0; p < 2; p++)
        boff[p] = bsAddr + (uint32_t)(((wn + p * 16 + ((lane >> 4) << 3) + (lane & 7)) * LDH
                                      + ((lane >> 3) & 1) * 8) * 2);

#define LDFRAG(st, ks) do { \
    uint32_t kb = (uint32_t)((ks) * 32); \
    _Pragma("unroll") \
    for (int mt = 0; mt < 2; mt++) \
        asm volatile("ldmatrix.sync.aligned.m8n8.x4.shared.b16 {%0,%1,%2,%3}, [%4];" \
            : "=r"(af[st][mt][0]), "=r"(af[st][mt][1]), "=r"(af[st][mt][2]), "=r"(af[st][mt][3]) \
            : "r"(aCur + aoff[mt] + kb)); \
    _Pragma("unroll") \
    for (int p = 0; p < 2; p++) \
        asm volatile("ldmatrix.sync.aligned.m8n8.x4.shared.b16 {%0,%1,%2,%3}, [%4];" \
            : "=r"(bf[st][p][0]), "=r"(bf[st][p][1]), "=r"(bf[st][p][2]), "=r"(bf[st][p][3]) \
            : "r"(boff[p] + kb)); \
} while (0)

    int buf = 0;
    for (;;) {
        int tn = t + GY;
        if (tn < tiles) {
            issueA(tn, buf ^ 1);
            asm volatile("cp.async.commit_group;" ::: "memory");
        }
        uint32_t aCur = aAddr[buf];
        float acc[2][4][4];
#pragma unroll
        for (int mt = 0; mt < 2; mt++)
#pragma unroll
            for (int nt = 0; nt < 4; nt++)
#pragma unroll
                for (int q = 0; q < 4; q++) acc[mt][nt][q] = 0.f;

        uint32_t af[2][2][4], bf[2][2][4];
        LDFRAG(0, 0);
#pragma unroll
        for (int ks = 0; ks < 8; ks++) {
            int cu = ks & 1;
            if (ks < 7) LDFRAG(cu ^ 1, ks + 1);
#pragma unroll
            for (int mt = 0; mt < 2; mt++)
#pragma unroll
                for (int nt = 0; nt < 4; nt++) {
                    int p = nt >> 1, s = (nt & 1) * 2;
                    mma_f16(acc[mt][nt], af[cu][mt], bf[cu][p][s], bf[cu][p][s + 1]);
                }
        }
        // epilogue
        int tm0 = t * 128;
#pragma unroll
        for (int mt = 0; mt < 2; mt++) {
            int r0 = tm0 + wm + mt * 16 + gid;
#pragma unroll
            for (int nt = 0; nt < 4; nt++) {
                int col = n0 + wn + nt * 8 + tig * 2;
                float2 bv = *(const float2*)&jb.bias[col];
                __half2 h0 = __floats2half2_rn(acc[mt][nt][0] + bv.x, acc[mt][nt][1] + bv.y);
                __half2 h1 = __floats2half2_rn(acc[mt][nt][2] + bv.x, acc[mt][nt][3] + bv.y);
                __stcs((unsigned int*)&jb.out[(size_t)r0 * HCc + col], *(unsigned int*)&h0);
                __stcs((unsigned int*)&jb.out[(size_t)(r0 + 8) * HCc + col], *(unsigned int*)&h1);
            }
        }
        if (tn >= tiles) break;
        asm volatile("cp.async.wait_group 0;" ::: "memory");
        __syncthreads();
        t = tn; buf ^= 1;
    }
#undef LDFRAG
}

// ---------------- elementwise kernels ----------------
__global__ void k_zero4(float4* __restrict__ p, int n4) {
    int i = blockIdx.x * blockDim.x + threadIdx.x;
    if (i < n4) p[i] = make_float4(0.f, 0.f, 0.f, 0.f);
}
__global__ void k_init_md(float* __restrict__ m, float* __restrict__ den, int n) {
    int i = blockIdx.x * blockDim.x + threadIdx.x;
    if (i < n) { m[i] = __int_as_float(0xff800000); den[i] = 0.f; }
}
// gather embedding row -> fp16
__global__ void k_embed(const int* __restrict__ idx, const float4* __restrict__ emb,
                        __half2* __restrict__ out, int n2) {  // n2 = rows*64 half2 pairs... indexed by float4 quads
    int i = blockIdx.x * blockDim.x + threadIdx.x;           // one float4 -> one half2x2 (store as 2 half2)
    if (i < n2) {
        float4 v = emb[idx[i >> 5] * 32 + (i & 31)];
        out[2 * i]     = __floats2half2_rn(v.x, v.y);
        out[2 * i + 1] = __floats2half2_rn(v.z, v.w);
    }
}
// cell = fp16(relu(acc + sum_r conv_bias))
__global__ void k_relu_bias(__half2* __restrict__ cell, const float4* __restrict__ acc,
                            const float* __restrict__ cb, int n4) {
    int i = blockIdx.x * blockDim.x + threadIdx.x;
    if (i < n4) {
        int c = (i & 31) * 4;
        float4 a = acc[i];
        float x = fmaxf(a.x + cb[c + 0] + cb[128 + c + 0] + cb[256 + c + 0], 0.f);
        float y = fmaxf(a.y + cb[c + 1] + cb[128 + c + 1] + cb[256 + c + 1], 0.f);
        float z = fmaxf(a.z + cb[c + 2] + cb[128 + c + 2] + cb[256 + c + 2], 0.f);
        float w = fmaxf(a.w + cb[c + 3] + cb[128 + c + 3] + cb[256 + c + 3], 0.f);
        cell[2 * i]     = __floats2half2_rn(x, y);
        cell[2 * i + 1] = __floats2half2_rn(z, w);
    }
}

// ---------------- batched edge kernels ----------------
struct EdgeBatch {
    const int* src[3]; const int* dst[3];
    const __half* xl[3]; const __half* xr[3];
    const float* att[3];
    float* sc[3]; float* m[3]; float* den[3];
    int E[3];
};

__global__ void k_score_b(EdgeBatch P) {
    int z = blockIdx.z;
    int e = blockIdx.x * (blockDim.x >> 5) + (threadIdx.x >> 5);
    int lane = threadIdx.x & 31;
    if (e >= P.E[z]) return;
    int s = P.src[z][e], d = P.dst[z][e];
    const __half2* xls = (const __half2*)P.xl[z] + (size_t)s * 256;
    const __half2* xrd = (const __half2*)P.xr[z] + (size_t)d * 256;
    const float* att = P.att[z];
    float part[4] = {0.f, 0.f, 0.f, 0.f};
#pragma unroll
    for (int h = 0; h < 4; h++)
#pragma unroll
        for (int k = 0; k < 2; k++) {
            int idx = h * 64 + k * 32 + lane;
            float2 a2 = __half22float2(xls[idx]);
            float2 b2 = __half22float2(xrd[idx]);
            float vx = a2.x + b2.x, vy = a2.y + b2.y;
            vx = vx > 0.f ? vx : SLOPEc * vx;
            vy = vy > 0.f ? vy : SLOPEc * vy;
            float2 at = *(const float2*)&att[2 * idx];
            part[h] += vx * at.x + vy * at.y;
        }
#pragma unroll
    for (int h = 0; h < 4; h++) {
        float v = part[h];
#pragma unroll
        for (int off = 16; off; off >>= 1) v += __shfl_down_sync(0xffffffffu, v, off);
        if (lane == 0) {
            P.sc[z][e * 4 + h] = v;
            atomicMaxF(&P.m[z][d * 4 + h], v);
        }
    }
}

__global__ void k_softmax_b(EdgeBatch P) {
    int z = blockIdx.z;
    int i = blockIdx.x * blockDim.x + threadIdx.x;
    if (i >= P.E[z] * 4) return;
    int e = i >> 2, h = i & 3;
    int d = P.dst[z][e];
    float p = expf(P.sc[z][i] - P.m[z][d * 4 + h]);
    P.sc[z][i] = p;
    atomicAdd(&P.den[z][d * 4 + h], p);
}

__global__ void k_aggr_b(EdgeBatch P, float* __restrict__ acc) {
    int z = blockIdx.z;
    int e = blockIdx.x * (blockDim.x >> 5) + (threadIdx.x >> 5);
    int lane = threadIdx.x & 31;
    if (e >= P.E[z]) return;
    int s = P.src[z][e], d = P.dst[z][e];
    float alpha[4];
#pragma unroll
    for (int h = 0; h < 4; h++)
        alpha[h] = P.sc[z][e * 4 + h] / (P.den[z][d * 4 + h] + 1e-16f);
    const __half2* xls = (const __half2*)P.xl[z] + (size_t)s * 256;
    float* accd = acc + (size_t)d * Dc;
#pragma unroll
    for (int j = 0; j < 2; j++) {
        int cc = lane + 32 * j;
        float vx = 0.f, vy = 0.f;
#pragma unroll
        for (int h = 0; h < 4; h++) {
            float2 x = __half22float2(xls[h * 64 + cc]);
            vx += alpha[h] * x.x;
            vy += alpha[h] * x.y;
        }
        atomicAdd(&accd[2 * cc],     0.25f * vx);
        atomicAdd(&accd[2 * cc + 1], 0.25f * vy);
    }
}

// ---------------- pooling: block of 128 threads handles 64 rows ----------------
__global__ void k_pool(const __half* __restrict__ cell, const int* __restrict__ batch,
                       float* __restrict__ sums, float* __restrict__ cnts) {
    __shared__ __half sc[64 * 128];
    __shared__ int sb[64];
    int g = blockIdx.x;     // row block g: rows [g*64, g*64+64)
    int tid = threadIdx.x;  // 128
    const int4* src = (const int4*)(cell + (size_t)g * 64 * 128);
    int4* dst = (int4*)sc;
#pragma unroll
    for (int i = 0; i < 8; i++) dst[tid + i * 128] = src[tid + i * 128];
    if (tid < 64) sb[tid] = batch[g * 64 + tid];
    __syncthreads();
    float a = 0.f;
    float c = 0.f;
#pragma unroll 4
    for (int r = 0; r < 64; r++) {
        a += __half2float(sc[r * 128 + tid]);
        c += 1.f;
        if (r == 63 || sb[r + 1] != sb[r]) {
            atomicAdd(&sums[(size_t)sb[r] * Dc + tid], a);
            if (tid == 0) atomicAdd(&cnts[sb[r]], c);
            a = 0.f; c = 0.f;
        }
    }
}

// ---------------- heads ----------------
__global__ void k_head(const float* __restrict__ sums, const float* __restrict__ cnts,
                       const float* __restrict__ fc1W, const float* __restrict__ fc1b,
                       const float* __restrict__ polW, const float* __restrict__ polb,
                       const float* __restrict__ valW, const float* __restrict__ valb,
                       float* __restrict__ out_policy, float* __restrict__ out_value) {
    int b = blockIdx.x;
    int t = threadIdx.x;  // 64
    __shared__ float pooled[128];
    __shared__ float hsh[64];
    float cnt = fmaxf(cnts[b], 1.f);
    pooled[t]      = sums[b * Dc + t] / cnt;
    pooled[t + 64] = sums[b * Dc + 64 + t] / cnt;
    __syncthreads();
    float a = fc1b[t];
#pragma unroll 4
    for (int d = 0; d < 128; d++) a += pooled[d] * fc1W[d * 64 + t];
    hsh[t] = fmaxf(a, 0.f);
    __syncthreads();
    if (t < BWc) {
        float a2 = polb[t];
#pragma unroll 4
        for (int k = 0; k < 64; k++) a2 += hsh[k] * polW[k * BWc + t];
        out_policy[b * BWc + t] = a2;
    }
    if (t == 8) {
        float a2 = valb[0];
#pragma unroll 4
        for (int k = 0; k < 64; k++) a2 += hsh[k] * valW[k];
        out_value[b] = tanhf(a2);
    }
}

// ---------------- launch ----------------
extern "C" void kernel_launch(void* const* d_in, const int* in_sizes, int n_in,
                              void* d_out, int out_size) {
    const int* cell_x     = (const int*)d_in[0];
    const int* piece_x    = (const int*)d_in[1];
    const int* srcs[3]    = {(const int*)d_in[2], (const int*)d_in[4], (const int*)d_in[6]};
    const int* dsts[3]    = {(const int*)d_in[3], (const int*)d_in[5], (const int*)d_in[7]};
    const int  Es[3]      = {in_sizes[2], in_sizes[4], in_sizes[6]};
    const int* cell_batch = (const int*)d_in[8];
    const float* cell_emb  = (const float*)d_in[9];
    const float* piece_emb = (const float*)d_in[10];
    const float* Wl  = (const float*)d_in[11];
    const float* bl  = (const float*)d_in[12];
    const float* Wr  = (const float*)d_in[13];
    const float* br  = (const float*)d_in[14];
    const float* att = (const float*)d_in[15];
    const float* cb  = (const float*)d_in[16];
    const float* fc1W = (const float*)d_in[17];
    const float* fc1b = (const float*)d_in[18];
    const float* polW = (const float*)d_in[19];
    const float* polb = (const float*)d_in[20];
    const float* valW = (const float*)d_in[21];
    const float* valb = (const float*)d_in[22];

    const int NC = in_sizes[0];
    const int NP = in_sizes[1];

    float *p_acc, *p_sums, *p_cnts, *p_sc, *p_m, *p_den;
    __half *p_cell, *p_piece, *p_wt;
    __half *p_xl[3], *p_xr[3];
    cudaGetSymbolAddress((void**)&p_cell,  g_cell);
    cudaGetSymbolAddress((void**)&p_acc,   g_acc);
    cudaGetSymbolAddress((void**)&p_piece, g_piece);
    cudaGetSymbolAddress((void**)&p_xl[0], g_xl0);
    cudaGetSymbolAddress((void**)&p_xl[1], g_xl1);
    cudaGetSymbolAddress((void**)&p_xl[2], g_xl2);
    cudaGetSymbolAddress((void**)&p_xr[0], g_xr0);
    cudaGetSymbolAddress((void**)&p_xr[1], g_xr1);
    cudaGetSymbolAddress((void**)&p_xr[2], g_xr2);
    cudaGetSymbolAddress((void**)&p_sc,    g_sc);
    cudaGetSymbolAddress((void**)&p_m,     g_m);
    cudaGetSymbolAddress((void**)&p_den,   g_den);
    cudaGetSymbolAddress((void**)&p_sums,  g_sums);
    cudaGetSymbolAddress((void**)&p_cnts,  g_cnts);
    cudaGetSymbolAddress((void**)&p_wt,    g_wt);

    const int SMEM_GEMM = 3 * 128 * LDH * 2;  // 104448 B
    cudaFuncSetAttribute(k_gemm, cudaFuncAttributeMaxDynamicSharedMemorySize, SMEM_GEMM);

    const int T = 256;
    const size_t MATSZ = (size_t)Dc * HCc;

    k_wprep<<<dim3(16, 4, 12), dim3(32, 8)>>>(Wl, p_wt);
    k_wprep<<<dim3(16, 4, 12), dim3(32, 8)>>>(Wr, p_wt + 12 * MATSZ);

    k_embed<<<(NC * 32 + T - 1) / T, T>>>(cell_x, (const float4*)cell_emb, (__half2*)p_cell, NC * 32);
    k_embed<<<(NP * 32 + T - 1) / T, T>>>(piece_x, (const float4*)piece_emb, (__half2*)p_piece, NP * 32);

    for (int l = 0; l < Lc; l++) {
        k_zero4<<<(NC * 32 + T - 1) / T, T>>>((float4*)p_acc, NC * 32);

        GemmBatch gb;
        for (int z = 0; z < 6; z++) {
            int r = (z == 0 || z == 1) ? 0 : (z <= 3 ? 1 : 2);
            bool isL = (z == 0) || (z == 2) || (z == 4);
            int mat = l * 3 + r;
            gb.j[z].A     = (z == 0) ? p_piece : p_cell;
            gb.j[z].W     = p_wt + (isL ? mat : 12 + mat) * MATSZ;
            gb.j[z].bias  = (isL ? bl : br) + (size_t)mat * HCc;
            gb.j[z].out   = isL ? p_xl[r] : p_xr[r];
            gb.j[z].tiles = ((z == 0) ? NP : NC) / 128;
        }
        k_gemm<<<dim3(4, 37, 6), 512, SMEM_GEMM>>>(gb);

        k_init_md<<<(3 * NC * Hc + T - 1) / T, T>>>(p_m, p_den, 3 * NC * Hc);

        EdgeBatch eb;
        int Emax = 0;
        for (int r = 0; r < 3; r++) {
            eb.src[r] = srcs[r]; eb.dst[r] = dsts[r];
            eb.xl[r] = p_xl[r]; eb.xr[r] = p_xr[r];
            eb.att[r] = att + (size_t)(l * 3 + r) * HCc;
            eb.sc[r]  = p_sc  + (size_t)r * NCc * Hc;
            eb.m[r]   = p_m   + (size_t)r * NCc * Hc;
            eb.den[r] = p_den + (size_t)r * NCc * Hc;
            eb.E[r] = Es[r];
            if (Es[r] > Emax) Emax = Es[r];
        }
        int wpb = T / 32;
        k_score_b  <<<dim3((Emax + wpb - 1) / wpb, 1, 3), T>>>(eb);
        k_softmax_b<<<dim3((Emax * 4 + T - 1) / T, 1, 3), T>>>(eb);
        k_aggr_b   <<<dim3((Emax + wpb - 1) / wpb, 1, 3), T>>>(eb, p_acc);

        k_relu_bias<<<(NC * 32 + T - 1) / T, T>>>(
            (__half2*)p_cell, (const float4*)p_acc, cb + (size_t)l * 3 * Cc, NC * 32);
    }

    // global mean pool
    k_zero4<<<(Bc * 32 + T - 1) / T, T>>>((float4*)p_sums, Bc * 32);
    k_zero4<<<(Bc / 4 + T - 1) / T, T>>>((float4*)p_cnts, Bc / 4);
    k_pool<<<NC / 64, 128>>>(p_cell, cell_batch, p_sums, p_cnts);

    // heads
    float* out = (float*)d_out;
    k_head<<<Bc, 64>>>(p_sums, p_cnts, fc1W, fc1b, polW, polb, valW, valb,
                       out, out + (size_t)Bc * BWc);
}